// round 14
// baseline (speedup 1.0000x reference)
#include <cuda_runtime.h>
#include <cuda_bf16.h>
#include <cstdint>

#define BB 32
#define TT 64
#define SS 128
#define EE 256
#define HH 512
#define ENCC 512
#define VV 32000
#define NDEC 32   // blocks in persistent decode kernel (one wave, co-resident)

// ---------------- scratch (device globals; no allocation) ----------------
__device__ float g_gatesx[BB * TT * 4 * HH];        // 16 MB [b,t,4H] = emb@Wih^T + bias
__device__ float g_hhist[BB * TT * HH];             // 4 MB  h after step t: [b,t,h]
__device__ float g_proj_enc[BB * SS * HH];          // 8 MB  enc @ Wa^T
__device__ float g_proj2[BB * SS * HH];             // 8 MB  enc @ Wc_c^T
__device__ float g_att2[BB * TT * SS];              // 1 MB  att per (b,t)
__device__ float g_ho[BB * TT * HH];                // 4 MB
__device__ float g_bias2[4 * HH];                   // b_ih + b_hh
__device__ unsigned g_flags[TT][NDEC];              // distributed barrier flags
// MMA-fragment-order packed operands (precomputed; mainloop has NO smem staging):
// B' per block: [k8(64)][n(64)][tg(4)][q(4)] q=(hi,k0+tg)(hi,+4)(lo,)(lo,+4); 65536 words
__device__ uint32_t g_whh_pk[NDEC * 65536];         // 8 MB
// A' planes: [(k8*2+mt)(128)][g(8)][tg(4)][q(4)] q=colhalf*2+rowhalf; 16384 words/plane
__device__ uint32_t g_hplA[2][2][16384];            // [parity][hi/lo]

// ---------------- helpers ----------------
__device__ __forceinline__ uint32_t f2tf32(float x) {
    uint32_t r;
    asm("cvt.rna.tf32.f32 %0, %1;" : "=r"(r) : "f"(x));
    return r;
}

__device__ __forceinline__ void mma_tf32(float* d, const uint32_t* a, const uint32_t* b) {
    asm("mma.sync.aligned.m16n8k8.row.col.f32.tf32.tf32.f32 "
        "{%0,%1,%2,%3}, {%4,%5,%6,%7}, {%8,%9}, {%0,%1,%2,%3};"
        : "+f"(d[0]), "+f"(d[1]), "+f"(d[2]), "+f"(d[3])
        : "r"(a[0]), "r"(a[1]), "r"(a[2]), "r"(a[3]), "r"(b[0]), "r"(b[1]));
}

// MUFU-based sigmoid/tanh: 2-3 MUFU ops, abs err ~1e-6, correct saturation.
__device__ __forceinline__ float fsig(float x) {
    float e, r;
    asm("ex2.approx.f32 %0, %1;" : "=f"(e) : "f"(-x * 1.442695041f));
    asm("rcp.approx.f32 %0, %1;" : "=f"(r) : "f"(1.0f + e));
    return r;
}
__device__ __forceinline__ float ftanh(float x) {
    float e, r;
    asm("ex2.approx.f32 %0, %1;" : "=f"(e) : "f"(x * 2.885390082f));
    asm("rcp.approx.f32 %0, %1;" : "=f"(r) : "f"(1.0f + e));
    return 1.0f - 2.0f * r;
}

// ------- double-buffered tf32 GEMM: C[M,N] = A[M,K] @ B[N,K]^T (+bias) -----------
template <bool COMP, bool GATHER>
__global__ __launch_bounds__(256) void gemm_db(
    const float* __restrict__ A, int lda, const int* __restrict__ gidx,
    const float* __restrict__ B, int ldb,
    float* __restrict__ C, int ldc,
    const float* __restrict__ bias0, int K)
{
    constexpr int KT = COMP ? 16 : 32;
    constexpr int PAD = COMP ? 20 : 36;
    constexpr int PLANE = 128 * PAD;
    constexpr int NPL = COMP ? 2 : 1;
    constexpr int STG = NPL * PLANE;
    constexpr int C4 = KT / 4;
    constexpr int NL = (128 * C4) / 256;

    extern __shared__ uint32_t sm[];
    uint32_t* As = sm;
    uint32_t* Bs = sm + 2 * STG;

    const int tid = threadIdx.x;
    const int warp = tid >> 5, lane = tid & 31;
    const int g = lane >> 2, tg = lane & 3;
    const int wm = (warp & 1) * 64, wn = (warp >> 1) * 32;
    const long m0 = (long)blockIdx.y * 128, n0 = (long)blockIdx.x * 128;

    float acc[4][4][4];
#pragma unroll
    for (int i = 0; i < 4; i++)
#pragma unroll
        for (int j = 0; j < 4; j++)
#pragma unroll
            for (int q = 0; q < 4; q++) acc[i][j][q] = 0.0f;

    const int nk = K / KT;
    float4 ra[NL], rb[NL];

    auto ldg_tile = [&](int kt) {
#pragma unroll
        for (int i = 0; i < NL; i++) {
            int idx = i * 256 + tid;
            int row = idx / C4, c4 = idx % C4;
            const float* ap = GATHER ? (A + (size_t)gidx[m0 + row] * lda)
                                     : (A + (size_t)(m0 + row) * lda);
            ra[i] = *(const float4*)(ap + kt + c4 * 4);
            rb[i] = *(const float4*)(B + (size_t)(n0 + row) * ldb + kt + c4 * 4);
        }
    };
    auto sts_tile = [&](int stg) {
        uint32_t* as = As + stg * STG;
        uint32_t* bs = Bs + stg * STG;
#pragma unroll
        for (int i = 0; i < NL; i++) {
            int idx = i * 256 + tid;
            int row = idx / C4, c4 = idx % C4;
            uint32_t* da = &as[row * PAD + c4 * 4];
            uint32_t* db = &bs[row * PAD + c4 * 4];
            float av[4] = {ra[i].x, ra[i].y, ra[i].z, ra[i].w};
            float bv[4] = {rb[i].x, rb[i].y, rb[i].z, rb[i].w};
#pragma unroll
            for (int q = 0; q < 4; q++) {
                uint32_t ah = f2tf32(av[q]);
                uint32_t bh = f2tf32(bv[q]);
                da[q] = ah;
                db[q] = bh;
                if (COMP) {
                    da[q + PLANE] = f2tf32(av[q] - __uint_as_float(ah));
                    db[q + PLANE] = f2tf32(bv[q] - __uint_as_float(bh));
                }
            }
        }
    };

    ldg_tile(0);
    sts_tile(0);
    __syncthreads();

    for (int ki = 0; ki < nk; ki++) {
        const int cur = ki & 1;
        if (ki + 1 < nk) ldg_tile((ki + 1) * KT);

        const uint32_t* Ac = As + cur * STG;
        const uint32_t* Bc = Bs + cur * STG;
#pragma unroll
        for (int ks = 0; ks < KT / 8; ks++) {
            const int k0 = ks * 8;
            uint32_t ah[4][4], bh[4][2];
#pragma unroll
            for (int mt = 0; mt < 4; mt++) {
                int rb2 = wm + mt * 16;
                ah[mt][0] = Ac[(rb2 + g) * PAD + k0 + tg];
                ah[mt][1] = Ac[(rb2 + g + 8) * PAD + k0 + tg];
                ah[mt][2] = Ac[(rb2 + g) * PAD + k0 + tg + 4];
                ah[mt][3] = Ac[(rb2 + g + 8) * PAD + k0 + tg + 4];
            }
#pragma unroll
            for (int nt = 0; nt < 4; nt++) {
                int nb = wn + nt * 8 + g;
                bh[nt][0] = Bc[nb * PAD + k0 + tg];
                bh[nt][1] = Bc[nb * PAD + k0 + tg + 4];
            }
            if (COMP) {
                uint32_t al[4][4], bl[4][2];
#pragma unroll
                for (int mt = 0; mt < 4; mt++) {
                    int rb2 = wm + mt * 16;
                    al[mt][0] = Ac[PLANE + (rb2 + g) * PAD + k0 + tg];
                    al[mt][1] = Ac[PLANE + (rb2 + g + 8) * PAD + k0 + tg];
                    al[mt][2] = Ac[PLANE + (rb2 + g) * PAD + k0 + tg + 4];
                    al[mt][3] = Ac[PLANE + (rb2 + g + 8) * PAD + k0 + tg + 4];
                }
#pragma unroll
                for (int nt = 0; nt < 4; nt++) {
                    int nb = wn + nt * 8 + g;
                    bl[nt][0] = Bc[PLANE + nb * PAD + k0 + tg];
                    bl[nt][1] = Bc[PLANE + nb * PAD + k0 + tg + 4];
                }
#pragma unroll
                for (int mt = 0; mt < 4; mt++)
#pragma unroll
                    for (int nt = 0; nt < 4; nt++) {
                        mma_tf32(acc[mt][nt], ah[mt], bh[nt]);
                        mma_tf32(acc[mt][nt], al[mt], bh[nt]);
                        mma_tf32(acc[mt][nt], ah[mt], bl[nt]);
                    }
            } else {
#pragma unroll
                for (int mt = 0; mt < 4; mt++)
#pragma unroll
                    for (int nt = 0; nt < 4; nt++)
                        mma_tf32(acc[mt][nt], ah[mt], bh[nt]);
            }
        }

        if (ki + 1 < nk) sts_tile(1 - cur);
        __syncthreads();
    }

#pragma unroll
    for (int nt = 0; nt < 4; nt++) {
        long col = n0 + wn + nt * 8 + 2 * tg;
        float bv0 = bias0 ? bias0[col] : 0.0f;
        float bv1 = bias0 ? bias0[col + 1] : 0.0f;
#pragma unroll
        for (int mt = 0; mt < 4; mt++) {
            long row = m0 + wm + mt * 16 + g;
            float2 r0 = make_float2(acc[mt][nt][0] + bv0, acc[mt][nt][1] + bv1);
            float2 r1 = make_float2(acc[mt][nt][2] + bv0, acc[mt][nt][3] + bv1);
            *(float2*)(C + row * ldc + col) = r0;
            *(float2*)(C + (row + 8) * ldc + col) = r1;
        }
    }
}

// ---------------- fused prep: packed B' + bias + flags reset ---------------------
__global__ void k_prep_all(const float* __restrict__ Whh,
                           const float* __restrict__ bih,
                           const float* __restrict__ bhh) {
    if (blockIdx.x == 0) {
        for (int i = threadIdx.x; i < TT * NDEC; i += 256)
            ((unsigned*)g_flags)[i] = 0u;
        for (int i = threadIdx.x; i < 4 * HH; i += 256)
            g_bias2[i] = bih[i] + bhh[i];
    }
    int o4 = blockIdx.x * 256 + threadIdx.x;        // over 2048 rows * 128 float4
    if (o4 >= 2048 * 128) return;
    int r = o4 >> 7, c4 = o4 & 127;
    int z = r >> 9, jg = r & 511;
    int blk = jg >> 4;
    int n = z * 16 + (jg & 15);
    int k = c4 * 4;
    int k8 = k >> 3, colhalf = (k >> 2) & 1;
    float4 v = *((const float4*)(Whh + (size_t)r * HH) + c4);
    float av[4] = {v.x, v.y, v.z, v.w};
    uint32_t* dst = g_whh_pk + (size_t)blk * 65536 + k8 * 1024 + n * 16 + colhalf;
#pragma unroll
    for (int tg = 0; tg < 4; tg++) {
        uint32_t hi = f2tf32(av[tg]);
        dst[tg * 4]     = hi;                                    // q = 0*2 + colhalf
        dst[tg * 4 + 2] = f2tf32(av[tg] - __uint_as_float(hi));  // q = 1*2 + colhalf
    }
}

// h0 -> A' fragment planes, parity 0.
__global__ void k_prep_h0(const float* __restrict__ h0) {
    int idx = blockIdx.x * 256 + threadIdx.x;       // over 32*512 elements
    if (idx >= BB * HH) return;
    int b = idx >> 9, j = idx & 511;
    float v = h0[b * HH + j];
    int word = (((j >> 3) * 2 + (b >> 4)) * 128) + (b & 7) * 16 + (j & 3) * 4
             + ((j >> 2) & 1) * 2 + ((b >> 3) & 1);
    uint32_t hi = f2tf32(v);
    g_hplA[0][0][word] = hi;
    g_hplA[0][1][word] = f2tf32(v - __uint_as_float(hi));
}

// ---------------- persistent decode v5: distributed-flag barrier, cross-barrier --
// prefetch of gx+B, MUFU transcendentals, conflict-free reduce (stride 80).
// Warp w owns k in [w*64, w*64+64). dyn smem: 8*2560 + 512 floats = 83,968 B.
__global__ __launch_bounds__(256) void k_decode(const float* __restrict__ c0)
{
    extern __shared__ float dynf[];
    float* dmp = dynf;                  // [w][m(32) stride 80][n(64)]
    float* csh = dmp + 8 * 2560;        // 512 floats

    const int blk = blockIdx.x, tid = threadIdx.x;
    const int warp = tid >> 5, lane = tid & 31, g = lane >> 2, tg = lane & 3;
    const int jb = blk * 16;
    const int k8b = warp * 8;           // this warp's k8 range: k8b..k8b+7

    for (int u = tid; u < 512; u += 256)
        csh[u] = c0[(u >> 4) * HH + jb + (u & 15)];

    const uint4* Bp = (const uint4*)(g_whh_pk + (size_t)blk * 65536);

    uint4 aB[2][2][2], bB[2][8];
    float gx[2][4];

    auto ld_gx = [&](int t) {
#pragma unroll
        for (int rep = 0; rep < 2; rep++) {
            int u = tid + rep * 256;
            size_t gbase = ((size_t)(u >> 4) * TT + t) * (4 * HH) + jb + (u & 15);
            gx[rep][0] = __ldcg(&g_gatesx[gbase]);
            gx[rep][1] = __ldcg(&g_gatesx[gbase + HH]);
            gx[rep][2] = __ldcg(&g_gatesx[gbase + 2 * HH]);
            gx[rep][3] = __ldcg(&g_gatesx[gbase + 3 * HH]);
        }
    };
    auto ldB = [&](int k8, int p) {
#pragma unroll
        for (int nt = 0; nt < 8; nt++)
            bB[p][nt] = Bp[k8 * 256 + nt * 32 + lane];
    };

    // prologue prefetch: step-0 gates + B stage 0
    ld_gx(0);
    ldB(k8b, 0);
    __syncthreads();

    for (int t = 0; t < TT; t++) {
        const uint4* Ahc = (const uint4*)g_hplA[t & 1][0];
        const uint4* Alc = (const uint4*)g_hplA[t & 1][1];

        auto ldA = [&](int k8, int p) {
#pragma unroll
            for (int mt = 0; mt < 2; mt++) {
                aB[p][mt][0] = __ldcg(Ahc + (k8 * 2 + mt) * 32 + lane);
                aB[p][mt][1] = __ldcg(Alc + (k8 * 2 + mt) * 32 + lane);
            }
        };

        float acc[2][8][4];
#pragma unroll
        for (int mt = 0; mt < 2; mt++)
#pragma unroll
            for (int nt = 0; nt < 8; nt++)
#pragma unroll
                for (int q = 0; q < 4; q++) acc[mt][nt][q] = 0.0f;

        ldA(k8b, 0);                    // bB[0] already prefetched pre-barrier
#pragma unroll
        for (int ks = 0; ks < 8; ks++) {
            const int cur = ks & 1;
            if (ks + 1 < 8) { ldA(k8b + ks + 1, 1 - cur); ldB(k8b + ks + 1, 1 - cur); }
#pragma unroll
            for (int mt = 0; mt < 2; mt++) {
                uint32_t ah[4] = {aB[cur][mt][0].x, aB[cur][mt][0].y,
                                  aB[cur][mt][0].z, aB[cur][mt][0].w};
                uint32_t al[4] = {aB[cur][mt][1].x, aB[cur][mt][1].y,
                                  aB[cur][mt][1].z, aB[cur][mt][1].w};
#pragma unroll
                for (int nt = 0; nt < 8; nt++) {
                    uint32_t bh[2] = {bB[cur][nt].x, bB[cur][nt].y};
                    uint32_t bl[2] = {bB[cur][nt].z, bB[cur][nt].w};
                    mma_tf32(acc[mt][nt], ah, bh);
                    mma_tf32(acc[mt][nt], al, bh);
                    mma_tf32(acc[mt][nt], ah, bl);
                }
            }
        }

        // dump partial C [32 b, 64 n] for this warp's k-slice (stride 80)
#pragma unroll
        for (int mt = 0; mt < 2; mt++)
#pragma unroll
            for (int nt = 0; nt < 8; nt++) {
                int row = mt * 16 + g, col = nt * 8 + tg * 2;
                *(float2*)&dmp[warp * 2560 + row * 80 + col] =
                    make_float2(acc[mt][nt][0], acc[mt][nt][1]);
                *(float2*)&dmp[warp * 2560 + (row + 8) * 80 + col] =
                    make_float2(acc[mt][nt][2], acc[mt][nt][3]);
            }
        __syncthreads();

        // reduce 8 warps + LSTM pointwise; write h fp32 + A' fragment planes
        uint32_t* whi = g_hplA[(t + 1) & 1][0];
        uint32_t* wlo = g_hplA[(t + 1) & 1][1];
#pragma unroll
        for (int rep = 0; rep < 2; rep++) {
            int u = tid + rep * 256;
            int b = u >> 4, jj = u & 15;
            float gate[4];
#pragma unroll
            for (int z = 0; z < 4; z++) {
                float s = 0.0f;
#pragma unroll
                for (int w = 0; w < 8; w++)
                    s += dmp[w * 2560 + b * 80 + z * 16 + jj];
                gate[z] = s + gx[rep][z];
            }
            float cn = fsig(gate[1]) * csh[u] + fsig(gate[0]) * ftanh(gate[2]);
            float hn = fsig(gate[3]) * ftanh(cn);
            csh[u] = cn;
            int j = jb + jj;
            __stcg(&g_hhist[((size_t)b * TT + t) * HH + j], hn);
            int word = (((j >> 3) * 2 + (b >> 4)) * 128) + (b & 7) * 16 + (j & 3) * 4
                     + ((j >> 2) & 1) * 2 + ((b >> 3) & 1);
            uint32_t hi = f2tf32(hn);
            __stcg(&whi[word], hi);
            __stcg(&wlo[word], f2tf32(hn - __uint_as_float(hi)));
        }
        __threadfence();
        __syncthreads();
        if (tid == 0) atomicExch(&g_flags[t][blk], 1u);   // parallel arrival (own line)

        // cross-barrier prefetch: next step's gates + constant B stage 0
        int tp = (t + 1 < TT) ? t + 1 : t;
        ld_gx(tp);
        ldB(k8b, 0);

        if (t + 1 < TT) {
            if (tid < 32) {             // parallel poll: each lane owns one block's flag
                unsigned v;
                do { v = atomicAdd(&g_flags[t][lane], 0u); }
                while (__any_sync(0xFFFFFFFFu, v == 0u));
            }
            __syncthreads();
        }
    }
}

// ---------------- post-loop: scores + softmax (parallel over b) ----------
__global__ __launch_bounds__(256) void k_scores(const int* __restrict__ lens)
{
    extern __shared__ uint32_t dynsm[];
    uint32_t* Ah = dynsm;                 // 64*20
    uint32_t* Al = Ah + 64 * 20;
    uint32_t* Bh = Al + 64 * 20;          // 128*20
    uint32_t* Bl = Bh + 128 * 20;
    float* sc = (float*)dynsm;            // 64*132 overlay (phase-separated)

    const int b = blockIdx.x, tid = threadIdx.x;
    const int warp = tid >> 5, lane = tid & 31, g = lane >> 2, tg = lane & 3;
    const int wm = (warp & 1) * 32, wn = (warp >> 1) * 32;

    float acc[2][4][4];
#pragma unroll
    for (int i = 0; i < 2; i++)
#pragma unroll
        for (int j = 0; j < 4; j++)
#pragma unroll
            for (int q = 0; q < 4; q++) acc[i][j][q] = 0.0f;

    for (int kt = 0; kt < HH; kt += 16) {
        {
            int row = tid >> 2, c4 = tid & 3;
            float4 v = *((const float4*)(g_hhist + ((size_t)b * TT + row) * HH + kt) + c4);
            float av[4] = {v.x, v.y, v.z, v.w};
            uint32_t* da = &Ah[row * 20 + c4 * 4];
            uint32_t* dl = &Al[row * 20 + c4 * 4];
#pragma unroll
            for (int q = 0; q < 4; q++) {
                uint32_t h = f2tf32(av[q]);
                da[q] = h;
                dl[q] = f2tf32(av[q] - __uint_as_float(h));
            }
        }
#pragma unroll
        for (int i = 0; i < 2; i++) {
            int idx = i * 256 + tid;
            int row = idx >> 2, c4 = idx & 3;
            float4 v = *((const float4*)(g_proj_enc + ((size_t)b * SS + row) * HH + kt) + c4);
            float bv[4] = {v.x, v.y, v.z, v.w};
            uint32_t* db = &Bh[row * 20 + c4 * 4];
            uint32_t* dl = &Bl[row * 20 + c4 * 4];
#pragma unroll
            for (int q = 0; q < 4; q++) {
                uint32_t h = f2tf32(bv[q]);
                db[q] = h;
                dl[q] = f2tf32(bv[q] - __uint_as_float(h));
            }
        }
        __syncthreads();
#pragma unroll
        for (int ks = 0; ks < 2; ks++) {
            const int k0 = ks * 8;
            uint32_t ah[2][4], al2[2][4], bh[4][2], bl2[4][2];
#pragma unroll
            for (int mt = 0; mt < 2; mt++) {
                int rb = wm + mt * 16;
                ah[mt][0] = Ah[(rb + g) * 20 + k0 + tg];
                ah[mt][1] = Ah[(rb + g + 8) * 20 + k0 + tg];
                ah[mt][2] = Ah[(rb + g) * 20 + k0 + tg + 4];
                ah[mt][3] = Ah[(rb + g + 8) * 20 + k0 + tg + 4];
                al2[mt][0] = Al[(rb + g) * 20 + k0 + tg];
                al2[mt][1] = Al[(rb + g + 8) * 20 + k0 + tg];
                al2[mt][2] = Al[(rb + g) * 20 + k0 + tg + 4];
                al2[mt][3] = Al[(rb + g + 8) * 20 + k0 + tg + 4];
            }
#pragma unroll
            for (int nt = 0; nt < 4; nt++) {
                int nb = wn + nt * 8 + g;
                bh[nt][0] = Bh[nb * 20 + k0 + tg];
                bh[nt][1] = Bh[nb * 20 + k0 + tg + 4];
                bl2[nt][0] = Bl[nb * 20 + k0 + tg];
                bl2[nt][1] = Bl[nb * 20 + k0 + tg + 4];
            }
#pragma unroll
            for (int mt = 0; mt < 2; mt++)
#pragma unroll
                for (int nt = 0; nt < 4; nt++) {
                    mma_tf32(acc[mt][nt], ah[mt], bh[nt]);
                    mma_tf32(acc[mt][nt], al2[mt], bh[nt]);
                    mma_tf32(acc[mt][nt], ah[mt], bl2[nt]);
                }
        }
        __syncthreads();
    }

#pragma unroll
    for (int mt = 0; mt < 2; mt++)
#pragma unroll
        for (int nt = 0; nt < 4; nt++) {
            int row = wm + mt * 16 + g, col = wn + nt * 8 + 2 * tg;
            sc[row * 132 + col] = acc[mt][nt][0];
            sc[row * 132 + col + 1] = acc[mt][nt][1];
            sc[(row + 8) * 132 + col] = acc[mt][nt][2];
            sc[(row + 8) * 132 + col + 1] = acc[mt][nt][3];
        }
    __syncthreads();

    const int len = lens[b];
    for (int i = 0; i < 8; i++) {
        int t = warp * 8 + i;
        float v[4], mx = -3.0e38f;
#pragma unroll
        for (int q = 0; q < 4; q++) {
            int s = lane + q * 32;
            v[q] = (s < len) ? sc[t * 132 + s] : -3.0e38f;
            mx = fmaxf(mx, v[q]);
        }
        for (int off = 16; off > 0; off >>= 1)
            mx = fmaxf(mx, __shfl_xor_sync(0xFFFFFFFFu, mx, off));
        float e[4], sum = 0.0f;
#pragma unroll
        for (int q = 0; q < 4; q++) {
            int s = lane + q * 32;
            e[q] = (s < len) ? expf(v[q] - mx) : 0.0f;
            sum += e[q];
        }
        for (int off = 16; off > 0; off >>= 1)
            sum += __shfl_xor_sync(0xFFFFFFFFu, sum, off);
        float inv = 1.0f / sum;
#pragma unroll
        for (int q = 0; q < 4; q++)
            g_att2[((size_t)b * TT + t) * SS + lane + q * 32] = e[q] * inv;
    }
}

// ---------------- post-loop: HO += att @ proj2 (batched per b) ----------
__global__ __launch_bounds__(256) void k_ctx()
{
    __shared__ float att_sh[TT * SS];
    const int b = blockIdx.y, jt = blockIdx.x, tid = threadIdx.x;

    for (int i = tid; i < TT * SS / 4; i += 256)
        ((float4*)att_sh)[i] = ((const float4*)(g_att2 + (size_t)b * TT * SS))[i];
    __syncthreads();

    const int j = jt * 128 + (tid & 127);
    const int th = tid >> 7;
    float acc[32];
#pragma unroll
    for (int tt = 0; tt < 32; tt++) acc[tt] = 0.0f;

    const float* p2 = g_proj2 + (size_t)b * SS * HH + j;
    const float* ar = att_sh + (th * 32) * SS;
#pragma unroll 4
    for (int s = 0; s < SS; s++) {
        float v = p2[(size_t)s * HH];
#pragma unroll
        for (int tt = 0; tt < 32; tt++)
            acc[tt] += ar[tt * SS + s] * v;
    }
#pragma unroll
    for (int tt = 0; tt < 32; tt++) {
        size_t o = ((size_t)b * TT + th * 32 + tt) * HH + j;
        g_ho[o] += acc[tt];
    }
}

// ---------------- launcher ----------------
extern "C" void kernel_launch(void* const* d_in, const int* in_sizes, int n_in,
                              void* d_out, int out_size)
{
    const int* tok = (const int*)d_in[0];
    const float* enc = (const float*)d_in[1];
    const int* lens = (const int*)d_in[2];
    const float* h0 = (const float*)d_in[3];
    const float* c0 = (const float*)d_in[4];
    const float* emb = (const float*)d_in[5];
    const float* Wih = (const float*)d_in[6];
    const float* Whh = (const float*)d_in[7];
    const float* bih = (const float*)d_in[8];
    const float* bhh = (const float*)d_in[9];
    const float* Wa = (const float*)d_in[10];
    const float* Wcw = (const float*)d_in[11];
    const float* Wcb = (const float*)d_in[12];
    const float* Wow = (const float*)d_in[13];
    const float* Wob = (const float*)d_in[14];
    float* out = (float*)d_out;

    float *p_gatesx, *p_hhist, *p_proj, *p_proj2, *p_ho, *p_bias;
    cudaGetSymbolAddress((void**)&p_gatesx, g_gatesx);
    cudaGetSymbolAddress((void**)&p_hhist, g_hhist);
    cudaGetSymbolAddress((void**)&p_proj, g_proj_enc);
    cudaGetSymbolAddress((void**)&p_proj2, g_proj2);
    cudaGetSymbolAddress((void**)&p_ho, g_ho);
    cudaGetSymbolAddress((void**)&p_bias, g_bias2);

    // smem opt-ins (one per template instantiation!)
    const int NC_DYN = 2 * 2 * (128 * 36) * 4;          // 73,728 B
    const int CP_DYN = 2 * 2 * (2 * 128 * 20) * 4;      // 81,920 B
    cudaFuncSetAttribute(gemm_db<false, true>,  cudaFuncAttributeMaxDynamicSharedMemorySize, NC_DYN);
    cudaFuncSetAttribute(gemm_db<false, false>, cudaFuncAttributeMaxDynamicSharedMemorySize, NC_DYN);
    cudaFuncSetAttribute(gemm_db<true, false>,  cudaFuncAttributeMaxDynamicSharedMemorySize, CP_DYN);

    const int DEC_DYN = (8 * 2560 + 512) * 4;           // 83,968 B
    cudaFuncSetAttribute(k_decode, cudaFuncAttributeMaxDynamicSharedMemorySize, DEC_DYN);
    const int SC_DYN = 64 * 132 * 4;                    // 33,792 B
    cudaFuncSetAttribute(k_scores, cudaFuncAttributeMaxDynamicSharedMemorySize, SC_DYN);

    // Launch order puts k_decode at stream position 4 (ncu profiles launch #4).

    // #1: fused prep (packed B' + bias + flags reset)
    k_prep_all<<<(2048 * 128 + 255) / 256, 256>>>(Whh, bih, bhh);
    // #2: h0 fragment planes
    k_prep_h0<<<(BB * HH + 255) / 256, 256>>>(h0);
    // #3: A1 gates_x[B*T, 4H] = emb[tok] @ W_ih^T + (b_ih + b_hh)
    gemm_db<false, true><<<dim3(4 * HH / 128, BB * TT / 128), 256, NC_DYN>>>(
        emb, EE, tok, Wih, EE, p_gatesx, 4 * HH, p_bias, EE);
    // #4: persistent LSTM recurrence (64 steps) — ncu target
    k_decode<<<NDEC, 256, DEC_DYN>>>(c0);

    // #5: A2 proj_enc = enc @ Wa^T (compensated tf32)
    gemm_db<true, false><<<dim3(HH / 128, BB * SS / 128), 256, CP_DYN>>>(
        enc, ENCC, nullptr, Wa, ENCC, p_proj, HH, nullptr, ENCC);
    // #6: A3 proj2 = enc @ Wc_c^T (Wc_c = Wc_w[:, H:], row stride H+ENC)
    gemm_db<true, false><<<dim3(HH / 128, BB * SS / 128), 256, CP_DYN>>>(
        enc, ENCC, nullptr, Wcw + HH, HH + ENCC, p_proj2, HH, nullptr, ENCC);
    // #7: scores + softmax
    k_scores<<<BB, 256, SC_DYN>>>(lens);
    // #8: HO = Hhist @ Wc_h^T + Wcb (compensated tf32; Wc_h = Wc_w[:, :H])
    gemm_db<true, false><<<dim3(HH / 128, BB * TT / 128), 256, CP_DYN>>>(
        p_hhist, HH, nullptr, Wcw, HH + ENCC, p_ho, HH, Wcb, HH);
    // #9: HO += att @ proj2
    k_ctx<<<dim3(4, BB), 256>>>();
    // #10: D logits = HO @ Wo^T + Wo_b
    gemm_db<false, false><<<dim3(VV / 128, BB * TT / 128), 256, NC_DYN>>>(
        p_ho, HH, nullptr, Wow, HH, out, VV, Wob, HH);
}

// round 15
// speedup vs baseline: 1.4753x; 1.4753x over previous
#include <cuda_runtime.h>
#include <cuda_bf16.h>
#include <cstdint>

#define BB 32
#define TT 64
#define SS 128
#define EE 256
#define HH 512
#define ENCC 512
#define VV 32000
#define NDEC 32   // blocks in persistent decode kernel (one wave, co-resident)

// ---------------- scratch (device globals; no allocation) ----------------
__device__ float g_gatesx[BB * TT * 4 * HH];        // 16 MB [b,t,4H] = emb@Wih^T + bias
__device__ float g_hhist[BB * TT * HH];             // 4 MB  h after step t: [b,t,h]
__device__ float g_proj_enc[BB * SS * HH];          // 8 MB  enc @ Wa^T
__device__ float g_proj2[BB * SS * HH];             // 8 MB  enc @ Wc_c^T
__device__ float g_att2[BB * TT * SS];              // 1 MB  att per (b,t)
__device__ float g_ho[BB * TT * HH];                // 4 MB
__device__ float g_bias2[4 * HH];                   // b_ih + b_hh
__device__ unsigned g_bar[TT];                      // decode grid barrier counters
// MMA-fragment-order packed operands (precomputed; mainloop has NO smem staging):
// B' per block: [k8(64)][n(64)][tg(4)][q(4)] q=(hi,k0+tg)(hi,+4)(lo,)(lo,+4); 65536 words
__device__ uint32_t g_whh_pk[NDEC * 65536];         // 8 MB
// A' planes: [(k8*2+mt)(128)][g(8)][tg(4)][q(4)] q=colhalf*2+rowhalf; 16384 words/plane
__device__ uint32_t g_hplA[2][2][16384];            // [parity][hi/lo]

// ---------------- helpers ----------------
__device__ __forceinline__ uint32_t f2tf32(float x) {
    uint32_t r;
    asm("cvt.rna.tf32.f32 %0, %1;" : "=r"(r) : "f"(x));
    return r;
}

__device__ __forceinline__ void mma_tf32(float* d, const uint32_t* a, const uint32_t* b) {
    asm("mma.sync.aligned.m16n8k8.row.col.f32.tf32.tf32.f32 "
        "{%0,%1,%2,%3}, {%4,%5,%6,%7}, {%8,%9}, {%0,%1,%2,%3};"
        : "+f"(d[0]), "+f"(d[1]), "+f"(d[2]), "+f"(d[3])
        : "r"(a[0]), "r"(a[1]), "r"(a[2]), "r"(a[3]), "r"(b[0]), "r"(b[1]));
}

// MUFU-based sigmoid/tanh: 2-3 MUFU ops, abs err ~1e-6, correct saturation.
// (kept from v5 — pure epilogue arithmetic, no sync interaction)
__device__ __forceinline__ float fsig(float x) {
    float e, r;
    asm("ex2.approx.f32 %0, %1;" : "=f"(e) : "f"(-x * 1.442695041f));
    asm("rcp.approx.f32 %0, %1;" : "=f"(r) : "f"(1.0f + e));
    return r;
}
__device__ __forceinline__ float ftanh(float x) {
    float e, r;
    asm("ex2.approx.f32 %0, %1;" : "=f"(e) : "f"(x * 2.885390082f));
    asm("rcp.approx.f32 %0, %1;" : "=f"(r) : "f"(1.0f + e));
    return 1.0f - 2.0f * r;
}

// ------- double-buffered tf32 GEMM: C[M,N] = A[M,K] @ B[N,K]^T (+bias) -----------
template <bool COMP, bool GATHER>
__global__ __launch_bounds__(256) void gemm_db(
    const float* __restrict__ A, int lda, const int* __restrict__ gidx,
    const float* __restrict__ B, int ldb,
    float* __restrict__ C, int ldc,
    const float* __restrict__ bias0, int K)
{
    constexpr int KT = COMP ? 16 : 32;
    constexpr int PAD = COMP ? 20 : 36;
    constexpr int PLANE = 128 * PAD;
    constexpr int NPL = COMP ? 2 : 1;
    constexpr int STG = NPL * PLANE;
    constexpr int C4 = KT / 4;
    constexpr int NL = (128 * C4) / 256;

    extern __shared__ uint32_t sm[];
    uint32_t* As = sm;
    uint32_t* Bs = sm + 2 * STG;

    const int tid = threadIdx.x;
    const int warp = tid >> 5, lane = tid & 31;
    const int g = lane >> 2, tg = lane & 3;
    const int wm = (warp & 1) * 64, wn = (warp >> 1) * 32;
    const long m0 = (long)blockIdx.y * 128, n0 = (long)blockIdx.x * 128;

    float acc[4][4][4];
#pragma unroll
    for (int i = 0; i < 4; i++)
#pragma unroll
        for (int j = 0; j < 4; j++)
#pragma unroll
            for (int q = 0; q < 4; q++) acc[i][j][q] = 0.0f;

    const int nk = K / KT;
    float4 ra[NL], rb[NL];

    auto ldg_tile = [&](int kt) {
#pragma unroll
        for (int i = 0; i < NL; i++) {
            int idx = i * 256 + tid;
            int row = idx / C4, c4 = idx % C4;
            const float* ap = GATHER ? (A + (size_t)gidx[m0 + row] * lda)
                                     : (A + (size_t)(m0 + row) * lda);
            ra[i] = *(const float4*)(ap + kt + c4 * 4);
            rb[i] = *(const float4*)(B + (size_t)(n0 + row) * ldb + kt + c4 * 4);
        }
    };
    auto sts_tile = [&](int stg) {
        uint32_t* as = As + stg * STG;
        uint32_t* bs = Bs + stg * STG;
#pragma unroll
        for (int i = 0; i < NL; i++) {
            int idx = i * 256 + tid;
            int row = idx / C4, c4 = idx % C4;
            uint32_t* da = &as[row * PAD + c4 * 4];
            uint32_t* db = &bs[row * PAD + c4 * 4];
            float av[4] = {ra[i].x, ra[i].y, ra[i].z, ra[i].w};
            float bv[4] = {rb[i].x, rb[i].y, rb[i].z, rb[i].w};
#pragma unroll
            for (int q = 0; q < 4; q++) {
                uint32_t ah = f2tf32(av[q]);
                uint32_t bh = f2tf32(bv[q]);
                da[q] = ah;
                db[q] = bh;
                if (COMP) {
                    da[q + PLANE] = f2tf32(av[q] - __uint_as_float(ah));
                    db[q + PLANE] = f2tf32(bv[q] - __uint_as_float(bh));
                }
            }
        }
    };

    ldg_tile(0);
    sts_tile(0);
    __syncthreads();

    for (int ki = 0; ki < nk; ki++) {
        const int cur = ki & 1;
        if (ki + 1 < nk) ldg_tile((ki + 1) * KT);

        const uint32_t* Ac = As + cur * STG;
        const uint32_t* Bc = Bs + cur * STG;
#pragma unroll
        for (int ks = 0; ks < KT / 8; ks++) {
            const int k0 = ks * 8;
            uint32_t ah[4][4], bh[4][2];
#pragma unroll
            for (int mt = 0; mt < 4; mt++) {
                int rb2 = wm + mt * 16;
                ah[mt][0] = Ac[(rb2 + g) * PAD + k0 + tg];
                ah[mt][1] = Ac[(rb2 + g + 8) * PAD + k0 + tg];
                ah[mt][2] = Ac[(rb2 + g) * PAD + k0 + tg + 4];
                ah[mt][3] = Ac[(rb2 + g + 8) * PAD + k0 + tg + 4];
            }
#pragma unroll
            for (int nt = 0; nt < 4; nt++) {
                int nb = wn + nt * 8 + g;
                bh[nt][0] = Bc[nb * PAD + k0 + tg];
                bh[nt][1] = Bc[nb * PAD + k0 + tg + 4];
            }
            if (COMP) {
                uint32_t al[4][4], bl[4][2];
#pragma unroll
                for (int mt = 0; mt < 4; mt++) {
                    int rb2 = wm + mt * 16;
                    al[mt][0] = Ac[PLANE + (rb2 + g) * PAD + k0 + tg];
                    al[mt][1] = Ac[PLANE + (rb2 + g + 8) * PAD + k0 + tg];
                    al[mt][2] = Ac[PLANE + (rb2 + g) * PAD + k0 + tg + 4];
                    al[mt][3] = Ac[PLANE + (rb2 + g + 8) * PAD + k0 + tg + 4];
                }
#pragma unroll
                for (int nt = 0; nt < 4; nt++) {
                    int nb = wn + nt * 8 + g;
                    bl[nt][0] = Bc[PLANE + nb * PAD + k0 + tg];
                    bl[nt][1] = Bc[PLANE + nb * PAD + k0 + tg + 4];
                }
#pragma unroll
                for (int mt = 0; mt < 4; mt++)
#pragma unroll
                    for (int nt = 0; nt < 4; nt++) {
                        mma_tf32(acc[mt][nt], ah[mt], bh[nt]);
                        mma_tf32(acc[mt][nt], al[mt], bh[nt]);
                        mma_tf32(acc[mt][nt], ah[mt], bl[nt]);
                    }
            } else {
#pragma unroll
                for (int mt = 0; mt < 4; mt++)
#pragma unroll
                    for (int nt = 0; nt < 4; nt++)
                        mma_tf32(acc[mt][nt], ah[mt], bh[nt]);
            }
        }

        if (ki + 1 < nk) sts_tile(1 - cur);
        __syncthreads();
    }

#pragma unroll
    for (int nt = 0; nt < 4; nt++) {
        long col = n0 + wn + nt * 8 + 2 * tg;
        float bv0 = bias0 ? bias0[col] : 0.0f;
        float bv1 = bias0 ? bias0[col + 1] : 0.0f;
#pragma unroll
        for (int mt = 0; mt < 4; mt++) {
            long row = m0 + wm + mt * 16 + g;
            float2 r0 = make_float2(acc[mt][nt][0] + bv0, acc[mt][nt][1] + bv1);
            float2 r1 = make_float2(acc[mt][nt][2] + bv0, acc[mt][nt][3] + bv1);
            *(float2*)(C + row * ldc + col) = r0;
            *(float2*)(C + (row + 8) * ldc + col) = r1;
        }
    }
}

// ---------------- fused prep: packed B' + bias + barrier reset -------------------
// Whh row r = z*H + jg, col k  ->  block jg/16, n = z*16 + jg%16,
// word(in blk region) = k8*1024 + n*16 + tg*4 + (plane*2 + colhalf).
__global__ void k_prep_all(const float* __restrict__ Whh,
                           const float* __restrict__ bih,
                           const float* __restrict__ bhh) {
    if (blockIdx.x == 0) {
        if (threadIdx.x < TT) g_bar[threadIdx.x] = 0u;
        for (int i = threadIdx.x; i < 4 * HH; i += 256)
            g_bias2[i] = bih[i] + bhh[i];
    }
    int o4 = blockIdx.x * 256 + threadIdx.x;        // over 2048 rows * 128 float4
    if (o4 >= 2048 * 128) return;
    int r = o4 >> 7, c4 = o4 & 127;
    int z = r >> 9, jg = r & 511;
    int blk = jg >> 4;
    int n = z * 16 + (jg & 15);
    int k = c4 * 4;
    int k8 = k >> 3, colhalf = (k >> 2) & 1;
    float4 v = *((const float4*)(Whh + (size_t)r * HH) + c4);
    float av[4] = {v.x, v.y, v.z, v.w};
    uint32_t* dst = g_whh_pk + (size_t)blk * 65536 + k8 * 1024 + n * 16 + colhalf;
#pragma unroll
    for (int tg = 0; tg < 4; tg++) {
        uint32_t hi = f2tf32(av[tg]);
        dst[tg * 4]     = hi;                                    // q = 0*2 + colhalf
        dst[tg * 4 + 2] = f2tf32(av[tg] - __uint_as_float(hi));  // q = 1*2 + colhalf
    }
}

// h0 -> A' fragment planes, parity 0.
__global__ void k_prep_h0(const float* __restrict__ h0) {
    int idx = blockIdx.x * 256 + threadIdx.x;       // over 32*512 elements
    if (idx >= BB * HH) return;
    int b = idx >> 9, j = idx & 511;
    float v = h0[b * HH + j];
    int word = (((j >> 3) * 2 + (b >> 4)) * 128) + (b & 7) * 16 + (j & 3) * 4
             + ((j >> 2) & 1) * 2 + ((b >> 3) & 1);
    uint32_t hi = f2tf32(v);
    g_hplA[0][0][word] = hi;
    g_hplA[0][1][word] = f2tf32(v - __uint_as_float(hi));
}

// ---------------- persistent decode v4.1: round-13 structure + MUFU epilogue -----
// (round-14's distributed-flag barrier + in-release-path prefetch REGRESSED
//  decode 484->655 us; reverted to the single-counter atomic barrier and the
//  in-loop gx prefetch that measured 484 us. Only the MUFU transcendentals kept.)
// Warp w owns k in [w*64, w*64+64). dyn smem: 8*2304 + 512 floats = 75,776 B.
__global__ __launch_bounds__(256) void k_decode(const float* __restrict__ c0)
{
    extern __shared__ float dynf[];
    float* dmp = dynf;                  // [w][m(32) stride 72][n(64)]
    float* csh = dmp + 8 * 2304;        // 512 floats

    const int blk = blockIdx.x, tid = threadIdx.x;
    const int warp = tid >> 5, lane = tid & 31, g = lane >> 2, tg = lane & 3;
    const int jb = blk * 16;
    const int k8b = warp * 8;           // this warp's k8 range: k8b..k8b+7

    for (int u = tid; u < 512; u += 256)
        csh[u] = c0[(u >> 4) * HH + jb + (u & 15)];

    const uint4* Bp = (const uint4*)(g_whh_pk + (size_t)blk * 65536);
    __syncthreads();

    for (int t = 0; t < TT; t++) {
        const uint4* Ahc = (const uint4*)g_hplA[t & 1][0];
        const uint4* Alc = (const uint4*)g_hplA[t & 1][1];

        // prefetch this step's gates_x scalars (independent of h)
        float gx[2][4];
#pragma unroll
        for (int rep = 0; rep < 2; rep++) {
            int u = tid + rep * 256;
            size_t gbase = ((size_t)(u >> 4) * TT + t) * (4 * HH) + jb + (u & 15);
            gx[rep][0] = __ldcg(&g_gatesx[gbase]);
            gx[rep][1] = __ldcg(&g_gatesx[gbase + HH]);
            gx[rep][2] = __ldcg(&g_gatesx[gbase + 2 * HH]);
            gx[rep][3] = __ldcg(&g_gatesx[gbase + 3 * HH]);
        }

        float acc[2][8][4];
#pragma unroll
        for (int mt = 0; mt < 2; mt++)
#pragma unroll
            for (int nt = 0; nt < 8; nt++)
#pragma unroll
                for (int q = 0; q < 4; q++) acc[mt][nt][q] = 0.0f;

        uint4 aB[2][2][2], bB[2][8];    // [parity][...]
        auto ldA = [&](int k8, int p) {
#pragma unroll
            for (int mt = 0; mt < 2; mt++) {
                aB[p][mt][0] = __ldcg(Ahc + (k8 * 2 + mt) * 32 + lane);
                aB[p][mt][1] = __ldcg(Alc + (k8 * 2 + mt) * 32 + lane);
            }
        };
        auto ldB = [&](int k8, int p) {
#pragma unroll
            for (int nt = 0; nt < 8; nt++)
                bB[p][nt] = Bp[k8 * 256 + nt * 32 + lane];
        };

        ldA(k8b, 0);
        ldB(k8b, 0);
#pragma unroll
        for (int ks = 0; ks < 8; ks++) {
            const int cur = ks & 1;
            if (ks + 1 < 8) { ldA(k8b + ks + 1, 1 - cur); ldB(k8b + ks + 1, 1 - cur); }
#pragma unroll
            for (int mt = 0; mt < 2; mt++) {
                uint32_t ah[4] = {aB[cur][mt][0].x, aB[cur][mt][0].y,
                                  aB[cur][mt][0].z, aB[cur][mt][0].w};
                uint32_t al[4] = {aB[cur][mt][1].x, aB[cur][mt][1].y,
                                  aB[cur][mt][1].z, aB[cur][mt][1].w};
#pragma unroll
                for (int nt = 0; nt < 8; nt++) {
                    uint32_t bh[2] = {bB[cur][nt].x, bB[cur][nt].y};
                    uint32_t bl[2] = {bB[cur][nt].z, bB[cur][nt].w};
                    mma_tf32(acc[mt][nt], ah, bh);
                    mma_tf32(acc[mt][nt], al, bh);
                    mma_tf32(acc[mt][nt], ah, bl);
                }
            }
        }

        // dump partial C [32 b, 64 n] for this warp's k-slice (stride 72: conflict-free)
#pragma unroll
        for (int mt = 0; mt < 2; mt++)
#pragma unroll
            for (int nt = 0; nt < 8; nt++) {
                int row = mt * 16 + g, col = nt * 8 + tg * 2;
                *(float2*)&dmp[warp * 2304 + row * 72 + col] =
                    make_float2(acc[mt][nt][0], acc[mt][nt][1]);
                *(float2*)&dmp[warp * 2304 + (row + 8) * 72 + col] =
                    make_float2(acc[mt][nt][2], acc[mt][nt][3]);
            }
        __syncthreads();

        // reduce 8 warps + LSTM pointwise (MUFU); write h fp32 + A' fragment planes
        uint32_t* whi = g_hplA[(t + 1) & 1][0];
        uint32_t* wlo = g_hplA[(t + 1) & 1][1];
#pragma unroll
        for (int rep = 0; rep < 2; rep++) {
            int u = tid + rep * 256;
            int b = u >> 4, jj = u & 15;
            float gate[4];
#pragma unroll
            for (int z = 0; z < 4; z++) {
                float s = 0.0f;
#pragma unroll
                for (int w = 0; w < 8; w++)
                    s += dmp[w * 2304 + b * 72 + z * 16 + jj];
                gate[z] = s + gx[rep][z];
            }
            float cn = fsig(gate[1]) * csh[u] + fsig(gate[0]) * ftanh(gate[2]);
            float hn = fsig(gate[3]) * ftanh(cn);
            csh[u] = cn;
            int j = jb + jj;
            __stcg(&g_hhist[((size_t)b * TT + t) * HH + j], hn);
            int word = (((j >> 3) * 2 + (b >> 4)) * 128) + (b & 7) * 16 + (j & 3) * 4
                     + ((j >> 2) & 1) * 2 + ((b >> 3) & 1);
            uint32_t hi = f2tf32(hn);
            __stcg(&whi[word], hi);
            __stcg(&wlo[word], f2tf32(hn - __uint_as_float(hi)));
        }
        __threadfence();
        __syncthreads();
        if (tid == 0) {
            atomicAdd(&g_bar[t], 1u);
            while (atomicAdd(&g_bar[t], 0u) < NDEC) {}   // atomic RMW poll: coherent
        }
        __syncthreads();
    }
}

// ---------------- post-loop: scores + softmax (parallel over b) ----------
__global__ __launch_bounds__(256) void k_scores(const int* __restrict__ lens)
{
    extern __shared__ uint32_t dynsm[];
    uint32_t* Ah = dynsm;                 // 64*20
    uint32_t* Al = Ah + 64 * 20;
    uint32_t* Bh = Al + 64 * 20;          // 128*20
    uint32_t* Bl = Bh + 128 * 20;
    float* sc = (float*)dynsm;            // 64*132 overlay (phase-separated)

    const int b = blockIdx.x, tid = threadIdx.x;
    const int warp = tid >> 5, lane = tid & 31, g = lane >> 2, tg = lane & 3;
    const int wm = (warp & 1) * 32, wn = (warp >> 1) * 32;

    float acc[2][4][4];
#pragma unroll
    for (int i = 0; i < 2; i++)
#pragma unroll
        for (int j = 0; j < 4; j++)
#pragma unroll
            for (int q = 0; q < 4; q++) acc[i][j][q] = 0.0f;

    for (int kt = 0; kt < HH; kt += 16) {
        {
            int row = tid >> 2, c4 = tid & 3;
            float4 v = *((const float4*)(g_hhist + ((size_t)b * TT + row) * HH + kt) + c4);
            float av[4] = {v.x, v.y, v.z, v.w};
            uint32_t* da = &Ah[row * 20 + c4 * 4];
            uint32_t* dl = &Al[row * 20 + c4 * 4];
#pragma unroll
            for (int q = 0; q < 4; q++) {
                uint32_t h = f2tf32(av[q]);
                da[q] = h;
                dl[q] = f2tf32(av[q] - __uint_as_float(h));
            }
        }
#pragma unroll
        for (int i = 0; i < 2; i++) {
            int idx = i * 256 + tid;
            int row = idx >> 2, c4 = idx & 3;
            float4 v = *((const float4*)(g_proj_enc + ((size_t)b * SS + row) * HH + kt) + c4);
            float bv[4] = {v.x, v.y, v.z, v.w};
            uint32_t* db = &Bh[row * 20 + c4 * 4];
            uint32_t* dl = &Bl[row * 20 + c4 * 4];
#pragma unroll
            for (int q = 0; q < 4; q++) {
                uint32_t h = f2tf32(bv[q]);
                db[q] = h;
                dl[q] = f2tf32(bv[q] - __uint_as_float(h));
            }
        }
        __syncthreads();
#pragma unroll
        for (int ks = 0; ks < 2; ks++) {
            const int k0 = ks * 8;
            uint32_t ah[2][4], al2[2][4], bh[4][2], bl2[4][2];
#pragma unroll
            for (int mt = 0; mt < 2; mt++) {
                int rb = wm + mt * 16;
                ah[mt][0] = Ah[(rb + g) * 20 + k0 + tg];
                ah[mt][1] = Ah[(rb + g + 8) * 20 + k0 + tg];
                ah[mt][2] = Ah[(rb + g) * 20 + k0 + tg + 4];
                ah[mt][3] = Ah[(rb + g + 8) * 20 + k0 + tg + 4];
                al2[mt][0] = Al[(rb + g) * 20 + k0 + tg];
                al2[mt][1] = Al[(rb + g + 8) * 20 + k0 + tg];
                al2[mt][2] = Al[(rb + g) * 20 + k0 + tg + 4];
                al2[mt][3] = Al[(rb + g + 8) * 20 + k0 + tg + 4];
            }
#pragma unroll
            for (int nt = 0; nt < 4; nt++) {
                int nb = wn + nt * 8 + g;
                bh[nt][0] = Bh[nb * 20 + k0 + tg];
                bh[nt][1] = Bh[nb * 20 + k0 + tg + 4];
                bl2[nt][0] = Bl[nb * 20 + k0 + tg];
                bl2[nt][1] = Bl[nb * 20 + k0 + tg + 4];
            }
#pragma unroll
            for (int mt = 0; mt < 2; mt++)
#pragma unroll
                for (int nt = 0; nt < 4; nt++) {
                    mma_tf32(acc[mt][nt], ah[mt], bh[nt]);
                    mma_tf32(acc[mt][nt], al2[mt], bh[nt]);
                    mma_tf32(acc[mt][nt], ah[mt], bl2[nt]);
                }
        }
        __syncthreads();
    }

#pragma unroll
    for (int mt = 0; mt < 2; mt++)
#pragma unroll
        for (int nt = 0; nt < 4; nt++) {
            int row = wm + mt * 16 + g, col = wn + nt * 8 + 2 * tg;
            sc[row * 132 + col] = acc[mt][nt][0];
            sc[row * 132 + col + 1] = acc[mt][nt][1];
            sc[(row + 8) * 132 + col] = acc[mt][nt][2];
            sc[(row + 8) * 132 + col + 1] = acc[mt][nt][3];
        }
    __syncthreads();

    const int len = lens[b];
    for (int i = 0; i < 8; i++) {
        int t = warp * 8 + i;
        float v[4], mx = -3.0e38f;
#pragma unroll
        for (int q = 0; q < 4; q++) {
            int s = lane + q * 32;
            v[q] = (s < len) ? sc[t * 132 + s] : -3.0e38f;
            mx = fmaxf(mx, v[q]);
        }
        for (int off = 16; off > 0; off >>= 1)
            mx = fmaxf(mx, __shfl_xor_sync(0xFFFFFFFFu, mx, off));
        float e[4], sum = 0.0f;
#pragma unroll
        for (int q = 0; q < 4; q++) {
            int s = lane + q * 32;
            e[q] = (s < len) ? expf(v[q] - mx) : 0.0f;
            sum += e[q];
        }
        for (int off = 16; off > 0; off >>= 1)
            sum += __shfl_xor_sync(0xFFFFFFFFu, sum, off);
        float inv = 1.0f / sum;
#pragma unroll
        for (int q = 0; q < 4; q++)
            g_att2[((size_t)b * TT + t) * SS + lane + q * 32] = e[q] * inv;
    }
}

// ---------------- post-loop: HO += att @ proj2 (batched per b) ----------
__global__ __launch_bounds__(256) void k_ctx()
{
    __shared__ float att_sh[TT * SS];
    const int b = blockIdx.y, jt = blockIdx.x, tid = threadIdx.x;

    for (int i = tid; i < TT * SS / 4; i += 256)
        ((float4*)att_sh)[i] = ((const float4*)(g_att2 + (size_t)b * TT * SS))[i];
    __syncthreads();

    const int j = jt * 128 + (tid & 127);
    const int th = tid >> 7;
    float acc[32];
#pragma unroll
    for (int tt = 0; tt < 32; tt++) acc[tt] = 0.0f;

    const float* p2 = g_proj2 + (size_t)b * SS * HH + j;
    const float* ar = att_sh + (th * 32) * SS;
#pragma unroll 4
    for (int s = 0; s < SS; s++) {
        float v = p2[(size_t)s * HH];
#pragma unroll
        for (int tt = 0; tt < 32; tt++)
            acc[tt] += ar[tt * SS + s] * v;
    }
#pragma unroll
    for (int tt = 0; tt < 32; tt++) {
        size_t o = ((size_t)b * TT + th * 32 + tt) * HH + j;
        g_ho[o] += acc[tt];
    }
}

// ---------------- launcher ----------------
extern "C" void kernel_launch(void* const* d_in, const int* in_sizes, int n_in,
                              void* d_out, int out_size)
{
    const int* tok = (const int*)d_in[0];
    const float* enc = (const float*)d_in[1];
    const int* lens = (const int*)d_in[2];
    const float* h0 = (const float*)d_in[3];
    const float* c0 = (const float*)d_in[4];
    const float* emb = (const float*)d_in[5];
    const float* Wih = (const float*)d_in[6];
    const float* Whh = (const float*)d_in[7];
    const float* bih = (const float*)d_in[8];
    const float* bhh = (const float*)d_in[9];
    const float* Wa = (const float*)d_in[10];
    const float* Wcw = (const float*)d_in[11];
    const float* Wcb = (const float*)d_in[12];
    const float* Wow = (const float*)d_in[13];
    const float* Wob = (const float*)d_in[14];
    float* out = (float*)d_out;

    float *p_gatesx, *p_hhist, *p_proj, *p_proj2, *p_ho, *p_bias;
    cudaGetSymbolAddress((void**)&p_gatesx, g_gatesx);
    cudaGetSymbolAddress((void**)&p_hhist, g_hhist);
    cudaGetSymbolAddress((void**)&p_proj, g_proj_enc);
    cudaGetSymbolAddress((void**)&p_proj2, g_proj2);
    cudaGetSymbolAddress((void**)&p_ho, g_ho);
    cudaGetSymbolAddress((void**)&p_bias, g_bias2);

    // smem opt-ins (one per template instantiation!)
    const int NC_DYN = 2 * 2 * (128 * 36) * 4;          // 73,728 B
    const int CP_DYN = 2 * 2 * (2 * 128 * 20) * 4;      // 81,920 B
    cudaFuncSetAttribute(gemm_db<false, true>,  cudaFuncAttributeMaxDynamicSharedMemorySize, NC_DYN);
    cudaFuncSetAttribute(gemm_db<false, false>, cudaFuncAttributeMaxDynamicSharedMemorySize, NC_DYN);
    cudaFuncSetAttribute(gemm_db<true, false>,  cudaFuncAttributeMaxDynamicSharedMemorySize, CP_DYN);

    const int DEC_DYN = (8 * 2304 + 512) * 4;           // 75,776 B
    cudaFuncSetAttribute(k_decode, cudaFuncAttributeMaxDynamicSharedMemorySize, DEC_DYN);
    const int SC_DYN = 64 * 132 * 4;                    // 33,792 B
    cudaFuncSetAttribute(k_scores, cudaFuncAttributeMaxDynamicSharedMemorySize, SC_DYN);

    // Launch order puts k_decode at stream position 4 (ncu profiles launch #4).

    // #1: fused prep (packed B' + bias + barrier reset)
    k_prep_all<<<(2048 * 128 + 255) / 256, 256>>>(Whh, bih, bhh);
    // #2: h0 fragment planes
    k_prep_h0<<<(BB * HH + 255) / 256, 256>>>(h0);
    // #3: A1 gates_x[B*T, 4H] = emb[tok] @ W_ih^T + (b_ih + b_hh)
    gemm_db<false, true><<<dim3(4 * HH / 128, BB * TT / 128), 256, NC_DYN>>>(
        emb, EE, tok, Wih, EE, p_gatesx, 4 * HH, p_bias, EE);
    // #4: persistent LSTM recurrence (64 steps) — ncu target
    k_decode<<<NDEC, 256, DEC_DYN>>>(c0);

    // #5: A2 proj_enc = enc @ Wa^T (compensated tf32)
    gemm_db<true, false><<<dim3(HH / 128, BB * SS / 128), 256, CP_DYN>>>(
        enc, ENCC, nullptr, Wa, ENCC, p_proj, HH, nullptr, ENCC);
    // #6: A3 proj2 = enc @ Wc_c^T (Wc_c = Wc_w[:, H:], row stride H+ENC)
    gemm_db<true, false><<<dim3(HH / 128, BB * SS / 128), 256, CP_DYN>>>(
        enc, ENCC, nullptr, Wcw + HH, HH + ENCC, p_proj2, HH, nullptr, ENCC);
    // #7: scores + softmax
    k_scores<<<BB, 256, SC_DYN>>>(lens);
    // #8: HO = Hhist @ Wc_h^T + Wcb (compensated tf32; Wc_h = Wc_w[:, :H])
    gemm_db<true, false><<<dim3(HH / 128, BB * TT / 128), 256, CP_DYN>>>(
        p_hhist, HH, nullptr, Wcw, HH + ENCC, p_ho, HH, Wcb, HH);
    // #9: HO += att @ proj2
    k_ctx<<<dim3(4, BB), 256>>>();
    // #10: D logits = HO @ Wo^T + Wo_b
    gemm_db<false, false><<<dim3(VV / 128, BB * TT / 128), 256, NC_DYN>>>(
        p_ho, HH, nullptr, Wow, HH, out, VV, Wob, HH);
}

// round 16
// speedup vs baseline: 1.4941x; 1.0128x over previous
#include <cuda_runtime.h>
#include <cuda_bf16.h>
#include <cstdint>

#define BB 32
#define TT 64
#define SS 128
#define EE 256
#define HH 512
#define ENCC 512
#define VV 32000
#define NDEC 32   // blocks in persistent decode kernel (one wave, co-resident)

// ---------------- scratch (device globals; no allocation) ----------------
__device__ float g_gatesx[BB * TT * 4 * HH];        // 16 MB [b,t,4H] = emb@Wih^T + bias
__device__ float g_hhist[BB * TT * HH];             // 4 MB  h after step t: [b,t,h]
__device__ float g_proj_enc[BB * SS * HH];          // 8 MB  enc @ Wa^T
__device__ float g_proj2[BB * SS * HH];             // 8 MB  enc @ Wc_c^T
__device__ float g_att2[BB * TT * SS];              // 1 MB  att per (b,t)
__device__ float g_ho[BB * TT * HH];                // 4 MB  (stored pre-rounded to tf32)
__device__ float g_bias2[4 * HH];                   // b_ih + b_hh
__device__ float g_wo_r[(size_t)VV * HH];           // 64 MB Wo pre-rounded to tf32
__device__ unsigned g_bar[TT];                      // decode grid barrier counters
// MMA-fragment-order packed operands (precomputed; mainloop has NO smem staging):
// B' per block: [k8(64)][n(64)][tg(4)][q(4)] q=(hi,k0+tg)(hi,+4)(lo,)(lo,+4); 65536 words
__device__ uint32_t g_whh_pk[NDEC * 65536];         // 8 MB
// A' planes: [(k8*2+mt)(128)][g(8)][tg(4)][q(4)] q=colhalf*2+rowhalf; 16384 words/plane
__device__ uint32_t g_hplA[2][2][16384];            // [parity][hi/lo]

// ---------------- helpers ----------------
__device__ __forceinline__ uint32_t f2tf32(float x) {
    uint32_t r;
    asm("cvt.rna.tf32.f32 %0, %1;" : "=r"(r) : "f"(x));
    return r;
}

__device__ __forceinline__ void mma_tf32(float* d, const uint32_t* a, const uint32_t* b) {
    asm("mma.sync.aligned.m16n8k8.row.col.f32.tf32.tf32.f32 "
        "{%0,%1,%2,%3}, {%4,%5,%6,%7}, {%8,%9}, {%0,%1,%2,%3};"
        : "+f"(d[0]), "+f"(d[1]), "+f"(d[2]), "+f"(d[3])
        : "r"(a[0]), "r"(a[1]), "r"(a[2]), "r"(a[3]), "r"(b[0]), "r"(b[1]));
}

// MUFU-based sigmoid/tanh: 2-3 MUFU ops, abs err ~1e-6, correct saturation.
__device__ __forceinline__ float fsig(float x) {
    float e, r;
    asm("ex2.approx.f32 %0, %1;" : "=f"(e) : "f"(-x * 1.442695041f));
    asm("rcp.approx.f32 %0, %1;" : "=f"(r) : "f"(1.0f + e));
    return r;
}
__device__ __forceinline__ float ftanh(float x) {
    float e, r;
    asm("ex2.approx.f32 %0, %1;" : "=f"(e) : "f"(x * 2.885390082f));
    asm("rcp.approx.f32 %0, %1;" : "=f"(r) : "f"(1.0f + e));
    return 1.0f - 2.0f * r;
}

// ------- double-buffered tf32 GEMM: C[M,N] = A[M,K] @ B[N,K]^T (+bias) -----------
// PRE: inputs already tf32-rounded (low mantissa bits zero) -> staging is a raw
// bit-copy, no cvt in the mainloop. Numerically identical (cvt is idempotent).
template <bool COMP, bool GATHER, bool PRE>
__global__ __launch_bounds__(256) void gemm_db(
    const float* __restrict__ A, int lda, const int* __restrict__ gidx,
    const float* __restrict__ B, int ldb,
    float* __restrict__ C, int ldc,
    const float* __restrict__ bias0, int K)
{
    constexpr int KT = COMP ? 16 : 32;
    constexpr int PAD = COMP ? 20 : 36;
    constexpr int PLANE = 128 * PAD;
    constexpr int NPL = COMP ? 2 : 1;
    constexpr int STG = NPL * PLANE;
    constexpr int C4 = KT / 4;
    constexpr int NL = (128 * C4) / 256;

    extern __shared__ uint32_t sm[];
    uint32_t* As = sm;
    uint32_t* Bs = sm + 2 * STG;

    const int tid = threadIdx.x;
    const int warp = tid >> 5, lane = tid & 31;
    const int g = lane >> 2, tg = lane & 3;
    const int wm = (warp & 1) * 64, wn = (warp >> 1) * 32;
    const long m0 = (long)blockIdx.y * 128, n0 = (long)blockIdx.x * 128;

    float acc[4][4][4];
#pragma unroll
    for (int i = 0; i < 4; i++)
#pragma unroll
        for (int j = 0; j < 4; j++)
#pragma unroll
            for (int q = 0; q < 4; q++) acc[i][j][q] = 0.0f;

    const int nk = K / KT;
    float4 ra[NL], rb[NL];

    auto ldg_tile = [&](int kt) {
#pragma unroll
        for (int i = 0; i < NL; i++) {
            int idx = i * 256 + tid;
            int row = idx / C4, c4 = idx % C4;
            const float* ap = GATHER ? (A + (size_t)gidx[m0 + row] * lda)
                                     : (A + (size_t)(m0 + row) * lda);
            ra[i] = *(const float4*)(ap + kt + c4 * 4);
            rb[i] = *(const float4*)(B + (size_t)(n0 + row) * ldb + kt + c4 * 4);
        }
    };
    auto sts_tile = [&](int stg) {
        uint32_t* as = As + stg * STG;
        uint32_t* bs = Bs + stg * STG;
#pragma unroll
        for (int i = 0; i < NL; i++) {
            int idx = i * 256 + tid;
            int row = idx / C4, c4 = idx % C4;
            uint32_t* da = &as[row * PAD + c4 * 4];
            uint32_t* db = &bs[row * PAD + c4 * 4];
            if (PRE) {
                // raw bit-copy: inputs already tf32-rounded
                da[0] = __float_as_uint(ra[i].x);
                da[1] = __float_as_uint(ra[i].y);
                da[2] = __float_as_uint(ra[i].z);
                da[3] = __float_as_uint(ra[i].w);
                db[0] = __float_as_uint(rb[i].x);
                db[1] = __float_as_uint(rb[i].y);
                db[2] = __float_as_uint(rb[i].z);
                db[3] = __float_as_uint(rb[i].w);
            } else {
                float av[4] = {ra[i].x, ra[i].y, ra[i].z, ra[i].w};
                float bv[4] = {rb[i].x, rb[i].y, rb[i].z, rb[i].w};
#pragma unroll
                for (int q = 0; q < 4; q++) {
                    uint32_t ah = f2tf32(av[q]);
                    uint32_t bh = f2tf32(bv[q]);
                    da[q] = ah;
                    db[q] = bh;
                    if (COMP) {
                        da[q + PLANE] = f2tf32(av[q] - __uint_as_float(ah));
                        db[q + PLANE] = f2tf32(bv[q] - __uint_as_float(bh));
                    }
                }
            }
        }
    };

    ldg_tile(0);
    sts_tile(0);
    __syncthreads();

    for (int ki = 0; ki < nk; ki++) {
        const int cur = ki & 1;
        if (ki + 1 < nk) ldg_tile((ki + 1) * KT);

        const uint32_t* Ac = As + cur * STG;
        const uint32_t* Bc = Bs + cur * STG;
#pragma unroll
        for (int ks = 0; ks < KT / 8; ks++) {
            const int k0 = ks * 8;
            uint32_t ah[4][4], bh[4][2];
#pragma unroll
            for (int mt = 0; mt < 4; mt++) {
                int rb2 = wm + mt * 16;
                ah[mt][0] = Ac[(rb2 + g) * PAD + k0 + tg];
                ah[mt][1] = Ac[(rb2 + g + 8) * PAD + k0 + tg];
                ah[mt][2] = Ac[(rb2 + g) * PAD + k0 + tg + 4];
                ah[mt][3] = Ac[(rb2 + g + 8) * PAD + k0 + tg + 4];
            }
#pragma unroll
            for (int nt = 0; nt < 4; nt++) {
                int nb = wn + nt * 8 + g;
                bh[nt][0] = Bc[nb * PAD + k0 + tg];
                bh[nt][1] = Bc[nb * PAD + k0 + tg + 4];
            }
            if (COMP) {
                uint32_t al[4][4], bl[4][2];
#pragma unroll
                for (int mt = 0; mt < 4; mt++) {
                    int rb2 = wm + mt * 16;
                    al[mt][0] = Ac[PLANE + (rb2 + g) * PAD + k0 + tg];
                    al[mt][1] = Ac[PLANE + (rb2 + g + 8) * PAD + k0 + tg];
                    al[mt][2] = Ac[PLANE + (rb2 + g) * PAD + k0 + tg + 4];
                    al[mt][3] = Ac[PLANE + (rb2 + g + 8) * PAD + k0 + tg + 4];
                }
#pragma unroll
                for (int nt = 0; nt < 4; nt++) {
                    int nb = wn + nt * 8 + g;
                    bl[nt][0] = Bc[PLANE + nb * PAD + k0 + tg];
                    bl[nt][1] = Bc[PLANE + nb * PAD + k0 + tg + 4];
                }
#pragma unroll
                for (int mt = 0; mt < 4; mt++)
#pragma unroll
                    for (int nt = 0; nt < 4; nt++) {
                        mma_tf32(acc[mt][nt], ah[mt], bh[nt]);
                        mma_tf32(acc[mt][nt], al[mt], bh[nt]);
                        mma_tf32(acc[mt][nt], ah[mt], bl[nt]);
                    }
            } else {
#pragma unroll
                for (int mt = 0; mt < 4; mt++)
#pragma unroll
                    for (int nt = 0; nt < 4; nt++)
                        mma_tf32(acc[mt][nt], ah[mt], bh[nt]);
            }
        }

        if (ki + 1 < nk) sts_tile(1 - cur);
        __syncthreads();
    }

#pragma unroll
    for (int nt = 0; nt < 4; nt++) {
        long col = n0 + wn + nt * 8 + 2 * tg;
        float bv0 = bias0 ? bias0[col] : 0.0f;
        float bv1 = bias0 ? bias0[col + 1] : 0.0f;
#pragma unroll
        for (int mt = 0; mt < 4; mt++) {
            long row = m0 + wm + mt * 16 + g;
            float2 r0 = make_float2(acc[mt][nt][0] + bv0, acc[mt][nt][1] + bv1);
            float2 r1 = make_float2(acc[mt][nt][2] + bv0, acc[mt][nt][3] + bv1);
            *(float2*)(C + row * ldc + col) = r0;
            *(float2*)(C + (row + 8) * ldc + col) = r1;
        }
    }
}

// ---------------- fused prep: packed B' + bias + barrier reset -------------------
__global__ void k_prep_all(const float* __restrict__ Whh,
                           const float* __restrict__ bih,
                           const float* __restrict__ bhh) {
    if (blockIdx.x == 0) {
        if (threadIdx.x < TT) g_bar[threadIdx.x] = 0u;
        for (int i = threadIdx.x; i < 4 * HH; i += 256)
            g_bias2[i] = bih[i] + bhh[i];
    }
    int o4 = blockIdx.x * 256 + threadIdx.x;        // over 2048 rows * 128 float4
    if (o4 >= 2048 * 128) return;
    int r = o4 >> 7, c4 = o4 & 127;
    int z = r >> 9, jg = r & 511;
    int blk = jg >> 4;
    int n = z * 16 + (jg & 15);
    int k = c4 * 4;
    int k8 = k >> 3, colhalf = (k >> 2) & 1;
    float4 v = *((const float4*)(Whh + (size_t)r * HH) + c4);
    float av[4] = {v.x, v.y, v.z, v.w};
    uint32_t* dst = g_whh_pk + (size_t)blk * 65536 + k8 * 1024 + n * 16 + colhalf;
#pragma unroll
    for (int tg = 0; tg < 4; tg++) {
        uint32_t hi = f2tf32(av[tg]);
        dst[tg * 4]     = hi;                                    // q = 0*2 + colhalf
        dst[tg * 4 + 2] = f2tf32(av[tg] - __uint_as_float(hi));  // q = 1*2 + colhalf
    }
}

// h0 -> A' fragment planes, parity 0.
__global__ void k_prep_h0(const float* __restrict__ h0) {
    int idx = blockIdx.x * 256 + threadIdx.x;       // over 32*512 elements
    if (idx >= BB * HH) return;
    int b = idx >> 9, j = idx & 511;
    float v = h0[b * HH + j];
    int word = (((j >> 3) * 2 + (b >> 4)) * 128) + (b & 7) * 16 + (j & 3) * 4
             + ((j >> 2) & 1) * 2 + ((b >> 3) & 1);
    uint32_t hi = f2tf32(v);
    g_hplA[0][0][word] = hi;
    g_hplA[0][1][word] = f2tf32(v - __uint_as_float(hi));
}

// Wo -> tf32-rounded copy (one-time; makes D's staging a pure bit-copy).
__global__ void k_prep_wo(const float* __restrict__ Wo) {
    size_t i4 = (size_t)blockIdx.x * 256 + threadIdx.x;   // float4 index
    if (i4 >= (size_t)VV * HH / 4) return;
    float4 v = ((const float4*)Wo)[i4];
    uint4 r;
    r.x = f2tf32(v.x);
    r.y = f2tf32(v.y);
    r.z = f2tf32(v.z);
    r.w = f2tf32(v.w);
    ((uint4*)g_wo_r)[i4] = r;
}

// ---------------- persistent decode v4.1 (round-15 known-good, unchanged) --------
__global__ __launch_bounds__(256) void k_decode(const float* __restrict__ c0)
{
    extern __shared__ float dynf[];
    float* dmp = dynf;                  // [w][m(32) stride 72][n(64)]
    float* csh = dmp + 8 * 2304;        // 512 floats

    const int blk = blockIdx.x, tid = threadIdx.x;
    const int warp = tid >> 5, lane = tid & 31, g = lane >> 2, tg = lane & 3;
    const int jb = blk * 16;
    const int k8b = warp * 8;           // this warp's k8 range: k8b..k8b+7

    for (int u = tid; u < 512; u += 256)
        csh[u] = c0[(u >> 4) * HH + jb + (u & 15)];

    const uint4* Bp = (const uint4*)(g_whh_pk + (size_t)blk * 65536);
    __syncthreads();

    for (int t = 0; t < TT; t++) {
        const uint4* Ahc = (const uint4*)g_hplA[t & 1][0];
        const uint4* Alc = (const uint4*)g_hplA[t & 1][1];

        // prefetch this step's gates_x scalars (independent of h)
        float gx[2][4];
#pragma unroll
        for (int rep = 0; rep < 2; rep++) {
            int u = tid + rep * 256;
            size_t gbase = ((size_t)(u >> 4) * TT + t) * (4 * HH) + jb + (u & 15);
            gx[rep][0] = __ldcg(&g_gatesx[gbase]);
            gx[rep][1] = __ldcg(&g_gatesx[gbase + HH]);
            gx[rep][2] = __ldcg(&g_gatesx[gbase + 2 * HH]);
            gx[rep][3] = __ldcg(&g_gatesx[gbase + 3 * HH]);
        }

        float acc[2][8][4];
#pragma unroll
        for (int mt = 0; mt < 2; mt++)
#pragma unroll
            for (int nt = 0; nt < 8; nt++)
#pragma unroll
                for (int q = 0; q < 4; q++) acc[mt][nt][q] = 0.0f;

        uint4 aB[2][2][2], bB[2][8];    // [parity][...]
        auto ldA = [&](int k8, int p) {
#pragma unroll
            for (int mt = 0; mt < 2; mt++) {
                aB[p][mt][0] = __ldcg(Ahc + (k8 * 2 + mt) * 32 + lane);
                aB[p][mt][1] = __ldcg(Alc + (k8 * 2 + mt) * 32 + lane);
            }
        };
        auto ldB = [&](int k8, int p) {
#pragma unroll
            for (int nt = 0; nt < 8; nt++)
                bB[p][nt] = Bp[k8 * 256 + nt * 32 + lane];
        };

        ldA(k8b, 0);
        ldB(k8b, 0);
#pragma unroll
        for (int ks = 0; ks < 8; ks++) {
            const int cur = ks & 1;
            if (ks + 1 < 8) { ldA(k8b + ks + 1, 1 - cur); ldB(k8b + ks + 1, 1 - cur); }
#pragma unroll
            for (int mt = 0; mt < 2; mt++) {
                uint32_t ah[4] = {aB[cur][mt][0].x, aB[cur][mt][0].y,
                                  aB[cur][mt][0].z, aB[cur][mt][0].w};
                uint32_t al[4] = {aB[cur][mt][1].x, aB[cur][mt][1].y,
                                  aB[cur][mt][1].z, aB[cur][mt][1].w};
#pragma unroll
                for (int nt = 0; nt < 8; nt++) {
                    uint32_t bh[2] = {bB[cur][nt].x, bB[cur][nt].y};
                    uint32_t bl[2] = {bB[cur][nt].z, bB[cur][nt].w};
                    mma_tf32(acc[mt][nt], ah, bh);
                    mma_tf32(acc[mt][nt], al, bh);
                    mma_tf32(acc[mt][nt], ah, bl);
                }
            }
        }

        // dump partial C [32 b, 64 n] for this warp's k-slice (stride 72: conflict-free)
#pragma unroll
        for (int mt = 0; mt < 2; mt++)
#pragma unroll
            for (int nt = 0; nt < 8; nt++) {
                int row = mt * 16 + g, col = nt * 8 + tg * 2;
                *(float2*)&dmp[warp * 2304 + row * 72 + col] =
                    make_float2(acc[mt][nt][0], acc[mt][nt][1]);
                *(float2*)&dmp[warp * 2304 + (row + 8) * 72 + col] =
                    make_float2(acc[mt][nt][2], acc[mt][nt][3]);
            }
        __syncthreads();

        // reduce 8 warps + LSTM pointwise (MUFU); write h fp32 + A' fragment planes
        uint32_t* whi = g_hplA[(t + 1) & 1][0];
        uint32_t* wlo = g_hplA[(t + 1) & 1][1];
#pragma unroll
        for (int rep = 0; rep < 2; rep++) {
            int u = tid + rep * 256;
            int b = u >> 4, jj = u & 15;
            float gate[4];
#pragma unroll
            for (int z = 0; z < 4; z++) {
                float s = 0.0f;
#pragma unroll
                for (int w = 0; w < 8; w++)
                    s += dmp[w * 2304 + b * 72 + z * 16 + jj];
                gate[z] = s + gx[rep][z];
            }
            float cn = fsig(gate[1]) * csh[u] + fsig(gate[0]) * ftanh(gate[2]);
            float hn = fsig(gate[3]) * ftanh(cn);
            csh[u] = cn;
            int j = jb + jj;
            __stcg(&g_hhist[((size_t)b * TT + t) * HH + j], hn);
            int word = (((j >> 3) * 2 + (b >> 4)) * 128) + (b & 7) * 16 + (j & 3) * 4
                     + ((j >> 2) & 1) * 2 + ((b >> 3) & 1);
            uint32_t hi = f2tf32(hn);
            __stcg(&whi[word], hi);
            __stcg(&wlo[word], f2tf32(hn - __uint_as_float(hi)));
        }
        __threadfence();
        __syncthreads();
        if (tid == 0) {
            atomicAdd(&g_bar[t], 1u);
            while (atomicAdd(&g_bar[t], 0u) < NDEC) {}   // atomic RMW poll: coherent
        }
        __syncthreads();
    }
}

// ---------------- post-loop: scores + softmax (parallel over b) ----------
__global__ __launch_bounds__(256) void k_scores(const int* __restrict__ lens)
{
    extern __shared__ uint32_t dynsm[];
    uint32_t* Ah = dynsm;                 // 64*20
    uint32_t* Al = Ah + 64 * 20;
    uint32_t* Bh = Al + 64 * 20;          // 128*20
    uint32_t* Bl = Bh + 128 * 20;
    float* sc = (float*)dynsm;            // 64*132 overlay (phase-separated)

    const int b = blockIdx.x, tid = threadIdx.x;
    const int warp = tid >> 5, lane = tid & 31, g = lane >> 2, tg = lane & 3;
    const int wm = (warp & 1) * 32, wn = (warp >> 1) * 32;

    float acc[2][4][4];
#pragma unroll
    for (int i = 0; i < 2; i++)
#pragma unroll
        for (int j = 0; j < 4; j++)
#pragma unroll
            for (int q = 0; q < 4; q++) acc[i][j][q] = 0.0f;

    for (int kt = 0; kt < HH; kt += 16) {
        {
            int row = tid >> 2, c4 = tid & 3;
            float4 v = *((const float4*)(g_hhist + ((size_t)b * TT + row) * HH + kt) + c4);
            float av[4] = {v.x, v.y, v.z, v.w};
            uint32_t* da = &Ah[row * 20 + c4 * 4];
            uint32_t* dl = &Al[row * 20 + c4 * 4];
#pragma unroll
            for (int q = 0; q < 4; q++) {
                uint32_t h = f2tf32(av[q]);
                da[q] = h;
                dl[q] = f2tf32(av[q] - __uint_as_float(h));
            }
        }
#pragma unroll
        for (int i = 0; i < 2; i++) {
            int idx = i * 256 + tid;
            int row = idx >> 2, c4 = idx & 3;
            float4 v = *((const float4*)(g_proj_enc + ((size_t)b * SS + row) * HH + kt) + c4);
            float bv[4] = {v.x, v.y, v.z, v.w};
            uint32_t* db = &Bh[row * 20 + c4 * 4];
            uint32_t* dl = &Bl[row * 20 + c4 * 4];
#pragma unroll
            for (int q = 0; q < 4; q++) {
                uint32_t h = f2tf32(bv[q]);
                db[q] = h;
                dl[q] = f2tf32(bv[q] - __uint_as_float(h));
            }
        }
        __syncthreads();
#pragma unroll
        for (int ks = 0; ks < 2; ks++) {
            const int k0 = ks * 8;
            uint32_t ah[2][4], al2[2][4], bh[4][2], bl2[4][2];
#pragma unroll
            for (int mt = 0; mt < 2; mt++) {
                int rb = wm + mt * 16;
                ah[mt][0] = Ah[(rb + g) * 20 + k0 + tg];
                ah[mt][1] = Ah[(rb + g + 8) * 20 + k0 + tg];
                ah[mt][2] = Ah[(rb + g) * 20 + k0 + tg + 4];
                ah[mt][3] = Ah[(rb + g + 8) * 20 + k0 + tg + 4];
                al2[mt][0] = Al[(rb + g) * 20 + k0 + tg];
                al2[mt][1] = Al[(rb + g + 8) * 20 + k0 + tg];
                al2[mt][2] = Al[(rb + g) * 20 + k0 + tg + 4];
                al2[mt][3] = Al[(rb + g + 8) * 20 + k0 + tg + 4];
            }
#pragma unroll
            for (int nt = 0; nt < 4; nt++) {
                int nb = wn + nt * 8 + g;
                bh[nt][0] = Bh[nb * 20 + k0 + tg];
                bh[nt][1] = Bh[nb * 20 + k0 + tg + 4];
                bl2[nt][0] = Bl[nb * 20 + k0 + tg];
                bl2[nt][1] = Bl[nb * 20 + k0 + tg + 4];
            }
#pragma unroll
            for (int mt = 0; mt < 2; mt++)
#pragma unroll
                for (int nt = 0; nt < 4; nt++) {
                    mma_tf32(acc[mt][nt], ah[mt], bh[nt]);
                    mma_tf32(acc[mt][nt], al2[mt], bh[nt]);
                    mma_tf32(acc[mt][nt], ah[mt], bl2[nt]);
                }
        }
        __syncthreads();
    }

#pragma unroll
    for (int mt = 0; mt < 2; mt++)
#pragma unroll
        for (int nt = 0; nt < 4; nt++) {
            int row = wm + mt * 16 + g, col = wn + nt * 8 + 2 * tg;
            sc[row * 132 + col] = acc[mt][nt][0];
            sc[row * 132 + col + 1] = acc[mt][nt][1];
            sc[(row + 8) * 132 + col] = acc[mt][nt][2];
            sc[(row + 8) * 132 + col + 1] = acc[mt][nt][3];
        }
    __syncthreads();

    const int len = lens[b];
    for (int i = 0; i < 8; i++) {
        int t = warp * 8 + i;
        float v[4], mx = -3.0e38f;
#pragma unroll
        for (int q = 0; q < 4; q++) {
            int s = lane + q * 32;
            v[q] = (s < len) ? sc[t * 132 + s] : -3.0e38f;
            mx = fmaxf(mx, v[q]);
        }
        for (int off = 16; off > 0; off >>= 1)
            mx = fmaxf(mx, __shfl_xor_sync(0xFFFFFFFFu, mx, off));
        float e[4], sum = 0.0f;
#pragma unroll
        for (int q = 0; q < 4; q++) {
            int s = lane + q * 32;
            e[q] = (s < len) ? expf(v[q] - mx) : 0.0f;
            sum += e[q];
        }
        for (int off = 16; off > 0; off >>= 1)
            sum += __shfl_xor_sync(0xFFFFFFFFu, sum, off);
        float inv = 1.0f / sum;
#pragma unroll
        for (int q = 0; q < 4; q++)
            g_att2[((size_t)b * TT + t) * SS + lane + q * 32] = e[q] * inv;
    }
}

// ---------------- post-loop: HO = tf32_round(HO + att @ proj2) ----------
// Rounds the final HO to tf32 so the D GEMM can stage it without conversion.
// Identical numerics: D previously applied the same cvt at staging time.
__global__ __launch_bounds__(256) void k_ctx()
{
    __shared__ float att_sh[TT * SS];
    const int b = blockIdx.y, jt = blockIdx.x, tid = threadIdx.x;

    for (int i = tid; i < TT * SS / 4; i += 256)
        ((float4*)att_sh)[i] = ((const float4*)(g_att2 + (size_t)b * TT * SS))[i];
    __syncthreads();

    const int j = jt * 128 + (tid & 127);
    const int th = tid >> 7;
    float acc[32];
#pragma unroll
    for (int tt = 0; tt < 32; tt++) acc[tt] = 0.0f;

    const float* p2 = g_proj2 + (size_t)b * SS * HH + j;
    const float* ar = att_sh + (th * 32) * SS;
#pragma unroll 4
    for (int s = 0; s < SS; s++) {
        float v = p2[(size_t)s * HH];
#pragma unroll
        for (int tt = 0; tt < 32; tt++)
            acc[tt] += ar[tt * SS + s] * v;
    }
#pragma unroll
    for (int tt = 0; tt < 32; tt++) {
        size_t o = ((size_t)b * TT + th * 32 + tt) * HH + j;
        g_ho[o] = __uint_as_float(f2tf32(g_ho[o] + acc[tt]));
    }
}

// ---------------- launcher ----------------
extern "C" void kernel_launch(void* const* d_in, const int* in_sizes, int n_in,
                              void* d_out, int out_size)
{
    const int* tok = (const int*)d_in[0];
    const float* enc = (const float*)d_in[1];
    const int* lens = (const int*)d_in[2];
    const float* h0 = (const float*)d_in[3];
    const float* c0 = (const float*)d_in[4];
    const float* emb = (const float*)d_in[5];
    const float* Wih = (const float*)d_in[6];
    const float* Whh = (const float*)d_in[7];
    const float* bih = (const float*)d_in[8];
    const float* bhh = (const float*)d_in[9];
    const float* Wa = (const float*)d_in[10];
    const float* Wcw = (const float*)d_in[11];
    const float* Wcb = (const float*)d_in[12];
    const float* Wow = (const float*)d_in[13];
    const float* Wob = (const float*)d_in[14];
    float* out = (float*)d_out;

    float *p_gatesx, *p_hhist, *p_proj, *p_proj2, *p_ho, *p_bias, *p_wor;
    cudaGetSymbolAddress((void**)&p_gatesx, g_gatesx);
    cudaGetSymbolAddress((void**)&p_hhist, g_hhist);
    cudaGetSymbolAddress((void**)&p_proj, g_proj_enc);
    cudaGetSymbolAddress((void**)&p_proj2, g_proj2);
    cudaGetSymbolAddress((void**)&p_ho, g_ho);
    cudaGetSymbolAddress((void**)&p_bias, g_bias2);
    cudaGetSymbolAddress((void**)&p_wor, g_wo_r);

    // smem opt-ins (one per template instantiation!)
    const int NC_DYN = 2 * 2 * (128 * 36) * 4;          // 73,728 B
    const int CP_DYN = 2 * 2 * (2 * 128 * 20) * 4;      // 81,920 B
    cudaFuncSetAttribute(gemm_db<false, true,  false>, cudaFuncAttributeMaxDynamicSharedMemorySize, NC_DYN);
    cudaFuncSetAttribute(gemm_db<false, false, true>,  cudaFuncAttributeMaxDynamicSharedMemorySize, NC_DYN);
    cudaFuncSetAttribute(gemm_db<true,  false, false>, cudaFuncAttributeMaxDynamicSharedMemorySize, CP_DYN);

    const int DEC_DYN = (8 * 2304 + 512) * 4;           // 75,776 B
    cudaFuncSetAttribute(k_decode, cudaFuncAttributeMaxDynamicSharedMemorySize, DEC_DYN);
    const int SC_DYN = 64 * 132 * 4;                    // 33,792 B
    cudaFuncSetAttribute(k_scores, cudaFuncAttributeMaxDynamicSharedMemorySize, SC_DYN);

    // Launch order puts k_decode at stream position 4 (ncu profiles launch #4).

    // #1: fused prep (packed B' + bias + barrier reset)
    k_prep_all<<<(2048 * 128 + 255) / 256, 256>>>(Whh, bih, bhh);
    // #2: h0 fragment planes
    k_prep_h0<<<(BB * HH + 255) / 256, 256>>>(h0);
    // #3: A1 gates_x[B*T, 4H] = emb[tok] @ W_ih^T + (b_ih + b_hh)
    gemm_db<false, true, false><<<dim3(4 * HH / 128, BB * TT / 128), 256, NC_DYN>>>(
        emb, EE, tok, Wih, EE, p_gatesx, 4 * HH, p_bias, EE);
    // #4: persistent LSTM recurrence (64 steps) — ncu target
    k_decode<<<NDEC, 256, DEC_DYN>>>(c0);

    // #5: Wo -> tf32-rounded copy (one-time)
    k_prep_wo<<<(int)(((size_t)VV * HH / 4 + 255) / 256), 256>>>(Wow);
    // #6: A2 proj_enc = enc @ Wa^T (compensated tf32)
    gemm_db<true, false, false><<<dim3(HH / 128, BB * SS / 128), 256, CP_DYN>>>(
        enc, ENCC, nullptr, Wa, ENCC, p_proj, HH, nullptr, ENCC);
    // #7: A3 proj2 = enc @ Wc_c^T (Wc_c = Wc_w[:, H:], row stride H+ENC)
    gemm_db<true, false, false><<<dim3(HH / 128, BB * SS / 128), 256, CP_DYN>>>(
        enc, ENCC, nullptr, Wcw + HH, HH + ENCC, p_proj2, HH, nullptr, ENCC);
    // #8: scores + softmax
    k_scores<<<BB, 256, SC_DYN>>>(lens);
    // #9: HO = Hhist @ Wc_h^T + Wcb (compensated tf32; Wc_h = Wc_w[:, :H])
    gemm_db<true, false, false><<<dim3(HH / 128, BB * TT / 128), 256, CP_DYN>>>(
        p_hhist, HH, nullptr, Wcw, HH + ENCC, p_ho, HH, Wcb, HH);
    // #10: HO = tf32_round(HO + att @ proj2)
    k_ctx<<<dim3(4, BB), 256>>>();
    // #11: D logits = HO @ Wo^T + Wo_b (pre-rounded operands: no cvt in mainloop)
    gemm_db<false, false, true><<<dim3(VV / 128, BB * TT / 128), 256, NC_DYN>>>(
        p_ho, HH, nullptr, p_wor, HH, out, VV, Wob, HH);
}

// round 17
// speedup vs baseline: 1.6704x; 1.1180x over previous
#include <cuda_runtime.h>
#include <cuda_bf16.h>
#include <cstdint>

#define BB 32
#define TT 64
#define SS 128
#define EE 256
#define HH 512
#define ENCC 512
#define VV 32000
#define NDEC 32   // decode blocks (one wave, co-resident)

// ---------------- scratch (device globals; no allocation) ----------------
__device__ float g_gatesx[BB * TT * 4 * HH];        // 16 MB [b,t,4H] = emb@Wih^T + bias
__device__ float g_hhist[BB * TT * HH];             // 4 MB  h after step t: [b,t,h]
__device__ float g_proj_enc[BB * SS * HH];          // 8 MB  enc @ Wa^T
__device__ float g_proj2[BB * SS * HH];             // 8 MB  enc @ Wc_c^T
__device__ float g_att2[BB * TT * SS];              // 1 MB  att per (b,t)
__device__ float g_ho[BB * TT * HH];                // 4 MB  (stored pre-rounded to tf32)
__device__ float g_bias2[4 * HH];                   // b_ih + b_hh
__device__ float g_wo_r[(size_t)VV * HH];           // 64 MB Wo pre-rounded to tf32
__device__ unsigned g_bar[TT];                      // decode grid barrier counters
// MMA-fragment-order packed operands:
__device__ uint32_t g_whh_pk[NDEC * 65536];         // 8 MB
__device__ uint32_t g_hplA[2][2][16384];            // [parity][hi/lo]

// ---------------- helpers ----------------
__device__ __forceinline__ uint32_t f2tf32(float x) {
    uint32_t r;
    asm("cvt.rna.tf32.f32 %0, %1;" : "=r"(r) : "f"(x));
    return r;
}

__device__ __forceinline__ void mma_tf32(float* d, const uint32_t* a, const uint32_t* b) {
    asm("mma.sync.aligned.m16n8k8.row.col.f32.tf32.tf32.f32 "
        "{%0,%1,%2,%3}, {%4,%5,%6,%7}, {%8,%9}, {%0,%1,%2,%3};"
        : "+f"(d[0]), "+f"(d[1]), "+f"(d[2]), "+f"(d[3])
        : "r"(a[0]), "r"(a[1]), "r"(a[2]), "r"(a[3]), "r"(b[0]), "r"(b[1]));
}

__device__ __forceinline__ float fsig(float x) {
    float e, r;
    asm("ex2.approx.f32 %0, %1;" : "=f"(e) : "f"(-x * 1.442695041f));
    asm("rcp.approx.f32 %0, %1;" : "=f"(r) : "f"(1.0f + e));
    return r;
}
__device__ __forceinline__ float ftanh(float x) {
    float e, r;
    asm("ex2.approx.f32 %0, %1;" : "=f"(e) : "f"(x * 2.885390082f));
    asm("rcp.approx.f32 %0, %1;" : "=f"(r) : "f"(1.0f + e));
    return 1.0f - 2.0f * r;
}

// ------- compensated tf32 GEMM tile body (device function; used by standalone
// kernel AND by the mega kernel's overlap blocks). C[128,128] tile at (m0,n0).
__device__ void gemm_comp_tile(
    uint32_t* sm, long m0, long n0,
    const float* __restrict__ A, int lda,
    const float* __restrict__ B, int ldb,
    float* __restrict__ C, int ldc,
    const float* __restrict__ bias0, int K)
{
    constexpr int KT = 16, PAD = 20, PLANE = 128 * PAD, STG = 2 * PLANE;
    constexpr int C4 = KT / 4, NL = (128 * C4) / 256;
    uint32_t* As = sm;
    uint32_t* Bs = sm + 2 * STG;

    const int tid = threadIdx.x;
    const int warp = tid >> 5, lane = tid & 31;
    const int g = lane >> 2, tg = lane & 3;
    const int wm = (warp & 1) * 64, wn = (warp >> 1) * 32;

    float acc[4][4][4];
#pragma unroll
    for (int i = 0; i < 4; i++)
#pragma unroll
        for (int j = 0; j < 4; j++)
#pragma unroll
            for (int q = 0; q < 4; q++) acc[i][j][q] = 0.0f;

    const int nk = K / KT;
    float4 ra[NL], rb[NL];

    auto ldg_tile = [&](int kt) {
#pragma unroll
        for (int i = 0; i < NL; i++) {
            int idx = i * 256 + tid;
            int row = idx / C4, c4 = idx % C4;
            ra[i] = *(const float4*)(A + (size_t)(m0 + row) * lda + kt + c4 * 4);
            rb[i] = *(const float4*)(B + (size_t)(n0 + row) * ldb + kt + c4 * 4);
        }
    };
    auto sts_tile = [&](int stg) {
        uint32_t* as = As + stg * STG;
        uint32_t* bs = Bs + stg * STG;
#pragma unroll
        for (int i = 0; i < NL; i++) {
            int idx = i * 256 + tid;
            int row = idx / C4, c4 = idx % C4;
            uint32_t* da = &as[row * PAD + c4 * 4];
            uint32_t* db = &bs[row * PAD + c4 * 4];
            float av[4] = {ra[i].x, ra[i].y, ra[i].z, ra[i].w};
            float bv[4] = {rb[i].x, rb[i].y, rb[i].z, rb[i].w};
#pragma unroll
            for (int q = 0; q < 4; q++) {
                uint32_t ah = f2tf32(av[q]);
                uint32_t bh = f2tf32(bv[q]);
                da[q] = ah;
                db[q] = bh;
                da[q + PLANE] = f2tf32(av[q] - __uint_as_float(ah));
                db[q + PLANE] = f2tf32(bv[q] - __uint_as_float(bh));
            }
        }
    };

    ldg_tile(0);
    sts_tile(0);
    __syncthreads();

    for (int ki = 0; ki < nk; ki++) {
        const int cur = ki & 1;
        if (ki + 1 < nk) ldg_tile((ki + 1) * KT);

        const uint32_t* Ac = As + cur * STG;
        const uint32_t* Bc = Bs + cur * STG;
#pragma unroll
        for (int ks = 0; ks < KT / 8; ks++) {
            const int k0 = ks * 8;
            uint32_t ah[4][4], bh[4][2], al[4][4], bl[4][2];
#pragma unroll
            for (int mt = 0; mt < 4; mt++) {
                int rb2 = wm + mt * 16;
                ah[mt][0] = Ac[(rb2 + g) * PAD + k0 + tg];
                ah[mt][1] = Ac[(rb2 + g + 8) * PAD + k0 + tg];
                ah[mt][2] = Ac[(rb2 + g) * PAD + k0 + tg + 4];
                ah[mt][3] = Ac[(rb2 + g + 8) * PAD + k0 + tg + 4];
                al[mt][0] = Ac[PLANE + (rb2 + g) * PAD + k0 + tg];
                al[mt][1] = Ac[PLANE + (rb2 + g + 8) * PAD + k0 + tg];
                al[mt][2] = Ac[PLANE + (rb2 + g) * PAD + k0 + tg + 4];
                al[mt][3] = Ac[PLANE + (rb2 + g + 8) * PAD + k0 + tg + 4];
            }
#pragma unroll
            for (int nt = 0; nt < 4; nt++) {
                int nb = wn + nt * 8 + g;
                bh[nt][0] = Bc[nb * PAD + k0 + tg];
                bh[nt][1] = Bc[nb * PAD + k0 + tg + 4];
                bl[nt][0] = Bc[PLANE + nb * PAD + k0 + tg];
                bl[nt][1] = Bc[PLANE + nb * PAD + k0 + tg + 4];
            }
#pragma unroll
            for (int mt = 0; mt < 4; mt++)
#pragma unroll
                for (int nt = 0; nt < 4; nt++) {
                    mma_tf32(acc[mt][nt], ah[mt], bh[nt]);
                    mma_tf32(acc[mt][nt], al[mt], bh[nt]);
                    mma_tf32(acc[mt][nt], ah[mt], bl[nt]);
                }
        }

        if (ki + 1 < nk) sts_tile(1 - cur);
        __syncthreads();
    }

#pragma unroll
    for (int nt = 0; nt < 4; nt++) {
        long col = n0 + wn + nt * 8 + 2 * tg;
        float bv0 = bias0 ? bias0[col] : 0.0f;
        float bv1 = bias0 ? bias0[col + 1] : 0.0f;
#pragma unroll
        for (int mt = 0; mt < 4; mt++) {
            long row = m0 + wm + mt * 16 + g;
            float2 r0 = make_float2(acc[mt][nt][0] + bv0, acc[mt][nt][1] + bv1);
            float2 r1 = make_float2(acc[mt][nt][2] + bv0, acc[mt][nt][3] + bv1);
            *(float2*)(C + row * ldc + col) = r0;
            *(float2*)(C + (row + 8) * ldc + col) = r1;
        }
    }
}

// standalone comp GEMM kernel (used for HO)
__global__ __launch_bounds__(256) void gemm_comp(
    const float* __restrict__ A, int lda,
    const float* __restrict__ B, int ldb,
    float* __restrict__ C, int ldc,
    const float* __restrict__ bias0, int K)
{
    extern __shared__ uint32_t sm[];
    gemm_comp_tile(sm, (long)blockIdx.y * 128, (long)blockIdx.x * 128,
                   A, lda, B, ldb, C, ldc, bias0, K);
}

// ------- non-comp double-buffered tf32 GEMM (A1 gather / D pre-rounded) ----------
template <bool GATHER, bool PRE>
__global__ __launch_bounds__(256) void gemm_nc(
    const float* __restrict__ A, int lda, const int* __restrict__ gidx,
    const float* __restrict__ B, int ldb,
    float* __restrict__ C, int ldc,
    const float* __restrict__ bias0, int K)
{
    constexpr int KT = 32, PAD = 36, PLANE = 128 * PAD, STG = PLANE;
    constexpr int C4 = KT / 4, NL = (128 * C4) / 256;

    extern __shared__ uint32_t sm[];
    uint32_t* As = sm;
    uint32_t* Bs = sm + 2 * STG;

    const int tid = threadIdx.x;
    const int warp = tid >> 5, lane = tid & 31;
    const int g = lane >> 2, tg = lane & 3;
    const int wm = (warp & 1) * 64, wn = (warp >> 1) * 32;
    const long m0 = (long)blockIdx.y * 128, n0 = (long)blockIdx.x * 128;

    float acc[4][4][4];
#pragma unroll
    for (int i = 0; i < 4; i++)
#pragma unroll
        for (int j = 0; j < 4; j++)
#pragma unroll
            for (int q = 0; q < 4; q++) acc[i][j][q] = 0.0f;

    const int nk = K / KT;
    float4 ra[NL], rb[NL];

    auto ldg_tile = [&](int kt) {
#pragma unroll
        for (int i = 0; i < NL; i++) {
            int idx = i * 256 + tid;
            int row = idx / C4, c4 = idx % C4;
            const float* ap = GATHER ? (A + (size_t)gidx[m0 + row] * lda)
                                     : (A + (size_t)(m0 + row) * lda);
            ra[i] = *(const float4*)(ap + kt + c4 * 4);
            rb[i] = *(const float4*)(B + (size_t)(n0 + row) * ldb + kt + c4 * 4);
        }
    };
    auto sts_tile = [&](int stg) {
        uint32_t* as = As + stg * STG;
        uint32_t* bs = Bs + stg * STG;
#pragma unroll
        for (int i = 0; i < NL; i++) {
            int idx = i * 256 + tid;
            int row = idx / C4, c4 = idx % C4;
            uint32_t* da = &as[row * PAD + c4 * 4];
            uint32_t* db = &bs[row * PAD + c4 * 4];
            if (PRE) {
                da[0] = __float_as_uint(ra[i].x);
                da[1] = __float_as_uint(ra[i].y);
                da[2] = __float_as_uint(ra[i].z);
                da[3] = __float_as_uint(ra[i].w);
                db[0] = __float_as_uint(rb[i].x);
                db[1] = __float_as_uint(rb[i].y);
                db[2] = __float_as_uint(rb[i].z);
                db[3] = __float_as_uint(rb[i].w);
            } else {
                float av[4] = {ra[i].x, ra[i].y, ra[i].z, ra[i].w};
                float bv[4] = {rb[i].x, rb[i].y, rb[i].z, rb[i].w};
#pragma unroll
                for (int q = 0; q < 4; q++) {
                    da[q] = f2tf32(av[q]);
                    db[q] = f2tf32(bv[q]);
                }
            }
        }
    };

    ldg_tile(0);
    sts_tile(0);
    __syncthreads();

    for (int ki = 0; ki < nk; ki++) {
        const int cur = ki & 1;
        if (ki + 1 < nk) ldg_tile((ki + 1) * KT);

        const uint32_t* Ac = As + cur * STG;
        const uint32_t* Bc = Bs + cur * STG;
#pragma unroll
        for (int ks = 0; ks < KT / 8; ks++) {
            const int k0 = ks * 8;
            uint32_t ah[4][4], bh[4][2];
#pragma unroll
            for (int mt = 0; mt < 4; mt++) {
                int rb2 = wm + mt * 16;
                ah[mt][0] = Ac[(rb2 + g) * PAD + k0 + tg];
                ah[mt][1] = Ac[(rb2 + g + 8) * PAD + k0 + tg];
                ah[mt][2] = Ac[(rb2 + g) * PAD + k0 + tg + 4];
                ah[mt][3] = Ac[(rb2 + g + 8) * PAD + k0 + tg + 4];
            }
#pragma unroll
            for (int nt = 0; nt < 4; nt++) {
                int nb = wn + nt * 8 + g;
                bh[nt][0] = Bc[nb * PAD + k0 + tg];
                bh[nt][1] = Bc[nb * PAD + k0 + tg + 4];
            }
#pragma unroll
            for (int mt = 0; mt < 4; mt++)
#pragma unroll
                for (int nt = 0; nt < 4; nt++)
                    mma_tf32(acc[mt][nt], ah[mt], bh[nt]);
        }

        if (ki + 1 < nk) sts_tile(1 - cur);
        __syncthreads();
    }

#pragma unroll
    for (int nt = 0; nt < 4; nt++) {
        long col = n0 + wn + nt * 8 + 2 * tg;
        float bv0 = bias0 ? bias0[col] : 0.0f;
        float bv1 = bias0 ? bias0[col + 1] : 0.0f;
#pragma unroll
        for (int mt = 0; mt < 4; mt++) {
            long row = m0 + wm + mt * 16 + g;
            float2 r0 = make_float2(acc[mt][nt][0] + bv0, acc[mt][nt][1] + bv1);
            float2 r1 = make_float2(acc[mt][nt][2] + bv0, acc[mt][nt][3] + bv1);
            *(float2*)(C + row * ldc + col) = r0;
            *(float2*)(C + (row + 8) * ldc + col) = r1;
        }
    }
}

// ---------------- fused prep: packed B' + bias + barrier reset -------------------
__global__ void k_prep_all(const float* __restrict__ Whh,
                           const float* __restrict__ bih,
                           const float* __restrict__ bhh) {
    if (blockIdx.x == 0) {
        if (threadIdx.x < TT) g_bar[threadIdx.x] = 0u;
        for (int i = threadIdx.x; i < 4 * HH; i += 256)
            g_bias2[i] = bih[i] + bhh[i];
    }
    int o4 = blockIdx.x * 256 + threadIdx.x;
    if (o4 >= 2048 * 128) return;
    int r = o4 >> 7, c4 = o4 & 127;
    int z = r >> 9, jg = r & 511;
    int blk = jg >> 4;
    int n = z * 16 + (jg & 15);
    int k = c4 * 4;
    int k8 = k >> 3, colhalf = (k >> 2) & 1;
    float4 v = *((const float4*)(Whh + (size_t)r * HH) + c4);
    float av[4] = {v.x, v.y, v.z, v.w};
    uint32_t* dst = g_whh_pk + (size_t)blk * 65536 + k8 * 1024 + n * 16 + colhalf;
#pragma unroll
    for (int tg = 0; tg < 4; tg++) {
        uint32_t hi = f2tf32(av[tg]);
        dst[tg * 4]     = hi;
        dst[tg * 4 + 2] = f2tf32(av[tg] - __uint_as_float(hi));
    }
}

// h0 -> A' fragment planes, parity 0.
__global__ void k_prep_h0(const float* __restrict__ h0) {
    int idx = blockIdx.x * 256 + threadIdx.x;
    if (idx >= BB * HH) return;
    int b = idx >> 9, j = idx & 511;
    float v = h0[b * HH + j];
    int word = (((j >> 3) * 2 + (b >> 4)) * 128) + (b & 7) * 16 + (j & 3) * 4
             + ((j >> 2) & 1) * 2 + ((b >> 3) & 1);
    uint32_t hi = f2tf32(v);
    g_hplA[0][0][word] = hi;
    g_hplA[0][1][word] = f2tf32(v - __uint_as_float(hi));
}

// ---------------- MEGA kernel: decode (blocks 0..31) ∥ A2/A3/prep_wo overlap ----
// blocks [32,160): A2 proj_enc tiles; [160,288): A3 proj2 tiles;
// [288,416): Wo->tf32 grid-stride. Overlap blocks never touch g_bar; the 32
// decode blocks are bids 0..31 -> guaranteed wave-1 co-residency (1 block/SM).
// dyn smem = 81,920 B (comp GEMM requirement; decode uses 75,776 of it).
__global__ __launch_bounds__(256) void k_mega(
    const float* __restrict__ c0,
    const float* __restrict__ enc,
    const float* __restrict__ Wa,
    const float* __restrict__ Wcw,
    const float* __restrict__ Wow)
{
    extern __shared__ uint32_t smw[];

    if (blockIdx.x >= NDEC) {
        int i = blockIdx.x - NDEC;
        if (i < 128) {                   // A2: proj_enc = enc @ Wa^T
            gemm_comp_tile(smw, (long)(i >> 2) * 128, (long)(i & 3) * 128,
                           enc, ENCC, Wa, ENCC, g_proj_enc, HH, nullptr, ENCC);
        } else if (i < 256) {            // A3: proj2 = enc @ Wc_c^T
            i -= 128;
            gemm_comp_tile(smw, (long)(i >> 2) * 128, (long)(i & 3) * 128,
                           enc, ENCC, Wcw + HH, HH + ENCC, g_proj2, HH, nullptr, ENCC);
        } else {                         // prep_wo: Wo -> tf32 (grid-stride)
            i -= 256;
            for (size_t i4 = (size_t)i * 256 + threadIdx.x;
                 i4 < (size_t)VV * HH / 4; i4 += (size_t)128 * 256) {
                float4 v = ((const float4*)Wow)[i4];
                uint4 r;
                r.x = f2tf32(v.x); r.y = f2tf32(v.y);
                r.z = f2tf32(v.z); r.w = f2tf32(v.w);
                ((uint4*)g_wo_r)[i4] = r;
            }
        }
        return;
    }

    // ---- decode path (round-15 known-good, verbatim) ----
    float* dynf = (float*)smw;
    float* dmp = dynf;                  // [w][m(32) stride 72][n(64)]
    float* csh = dmp + 8 * 2304;        // 512 floats

    const int blk = blockIdx.x, tid = threadIdx.x;
    const int warp = tid >> 5, lane = tid & 31, g = lane >> 2, tg = lane & 3;
    const int jb = blk * 16;
    const int k8b = warp * 8;

    for (int u = tid; u < 512; u += 256)
        csh[u] = c0[(u >> 4) * HH + jb + (u & 15)];

    const uint4* Bp = (const uint4*)(g_whh_pk + (size_t)blk * 65536);
    __syncthreads();

    for (int t = 0; t < TT; t++) {
        const uint4* Ahc = (const uint4*)g_hplA[t & 1][0];
        const uint4* Alc = (const uint4*)g_hplA[t & 1][1];

        float gx[2][4];
#pragma unroll
        for (int rep = 0; rep < 2; rep++) {
            int u = tid + rep * 256;
            size_t gbase = ((size_t)(u >> 4) * TT + t) * (4 * HH) + jb + (u & 15);
            gx[rep][0] = __ldcg(&g_gatesx[gbase]);
            gx[rep][1] = __ldcg(&g_gatesx[gbase + HH]);
            gx[rep][2] = __ldcg(&g_gatesx[gbase + 2 * HH]);
            gx[rep][3] = __ldcg(&g_gatesx[gbase + 3 * HH]);
        }

        float acc[2][8][4];
#pragma unroll
        for (int mt = 0; mt < 2; mt++)
#pragma unroll
            for (int nt = 0; nt < 8; nt++)
#pragma unroll
                for (int q = 0; q < 4; q++) acc[mt][nt][q] = 0.0f;

        uint4 aB[2][2][2], bB[2][8];
        auto ldA = [&](int k8, int p) {
#pragma unroll
            for (int mt = 0; mt < 2; mt++) {
                aB[p][mt][0] = __ldcg(Ahc + (k8 * 2 + mt) * 32 + lane);
                aB[p][mt][1] = __ldcg(Alc + (k8 * 2 + mt) * 32 + lane);
            }
        };
        auto ldB = [&](int k8, int p) {
#pragma unroll
            for (int nt = 0; nt < 8; nt++)
                bB[p][nt] = Bp[k8 * 256 + nt * 32 + lane];
        };

        ldA(k8b, 0);
        ldB(k8b, 0);
#pragma unroll
        for (int ks = 0; ks < 8; ks++) {
            const int cur = ks & 1;
            if (ks + 1 < 8) { ldA(k8b + ks + 1, 1 - cur); ldB(k8b + ks + 1, 1 - cur); }
#pragma unroll
            for (int mt = 0; mt < 2; mt++) {
                uint32_t ah[4] = {aB[cur][mt][0].x, aB[cur][mt][0].y,
                                  aB[cur][mt][0].z, aB[cur][mt][0].w};
                uint32_t al[4] = {aB[cur][mt][1].x, aB[cur][mt][1].y,
                                  aB[cur][mt][1].z, aB[cur][mt][1].w};
#pragma unroll
                for (int nt = 0; nt < 8; nt++) {
                    uint32_t bh[2] = {bB[cur][nt].x, bB[cur][nt].y};
                    uint32_t bl[2] = {bB[cur][nt].z, bB[cur][nt].w};
                    mma_tf32(acc[mt][nt], ah, bh);
                    mma_tf32(acc[mt][nt], al, bh);
                    mma_tf32(acc[mt][nt], ah, bl);
                }
            }
        }

#pragma unroll
        for (int mt = 0; mt < 2; mt++)
#pragma unroll
            for (int nt = 0; nt < 8; nt++) {
                int row = mt * 16 + g, col = nt * 8 + tg * 2;
                *(float2*)&dmp[warp * 2304 + row * 72 + col] =
                    make_float2(acc[mt][nt][0], acc[mt][nt][1]);
                *(float2*)&dmp[warp * 2304 + (row + 8) * 72 + col] =
                    make_float2(acc[mt][nt][2], acc[mt][nt][3]);
            }
        __syncthreads();

        uint32_t* whi = g_hplA[(t + 1) & 1][0];
        uint32_t* wlo = g_hplA[(t + 1) & 1][1];
#pragma unroll
        for (int rep = 0; rep < 2; rep++) {
            int u = tid + rep * 256;
            int b = u >> 4, jj = u & 15;
            float gate[4];
#pragma unroll
            for (int z = 0; z < 4; z++) {
                float s = 0.0f;
#pragma unroll
                for (int w = 0; w < 8; w++)
                    s += dmp[w * 2304 + b * 72 + z * 16 + jj];
                gate[z] = s + gx[rep][z];
            }
            float cn = fsig(gate[1]) * csh[u] + fsig(gate[0]) * ftanh(gate[2]);
            float hn = fsig(gate[3]) * ftanh(cn);
            csh[u] = cn;
            int j = jb + jj;
            __stcg(&g_hhist[((size_t)b * TT + t) * HH + j], hn);
            int word = (((j >> 3) * 2 + (b >> 4)) * 128) + (b & 7) * 16 + (j & 3) * 4
                     + ((j >> 2) & 1) * 2 + ((b >> 3) & 1);
            uint32_t hi = f2tf32(hn);
            __stcg(&whi[word], hi);
            __stcg(&wlo[word], f2tf32(hn - __uint_as_float(hi)));
        }
        __threadfence();
        __syncthreads();
        if (tid == 0) {
            atomicAdd(&g_bar[t], 1u);
            while (atomicAdd(&g_bar[t], 0u) < NDEC) {}   // atomic RMW poll: coherent
        }
        __syncthreads();
    }
}

// ---------------- post-loop: scores + softmax (parallel over b) ----------
__global__ __launch_bounds__(256) void k_scores(const int* __restrict__ lens)
{
    extern __shared__ uint32_t dynsm[];
    uint32_t* Ah = dynsm;                 // 64*20
    uint32_t* Al = Ah + 64 * 20;
    uint32_t* Bh = Al + 64 * 20;          // 128*20
    uint32_t* Bl = Bh + 128 * 20;
    float* sc = (float*)dynsm;            // 64*132 overlay (phase-separated)

    const int b = blockIdx.x, tid = threadIdx.x;
    const int warp = tid >> 5, lane = tid & 31, g = lane >> 2, tg = lane & 3;
    const int wm = (warp & 1) * 32, wn = (warp >> 1) * 32;

    float acc[2][4][4];
#pragma unroll
    for (int i = 0; i < 2; i++)
#pragma unroll
        for (int j = 0; j < 4; j++)
#pragma unroll
            for (int q = 0; q < 4; q++) acc[i][j][q] = 0.0f;

    for (int kt = 0; kt < HH; kt += 16) {
        {
            int row = tid >> 2, c4 = tid & 3;
            float4 v = *((const float4*)(g_hhist + ((size_t)b * TT + row) * HH + kt) + c4);
            float av[4] = {v.x, v.y, v.z, v.w};
            uint32_t* da = &Ah[row * 20 + c4 * 4];
            uint32_t* dl = &Al[row * 20 + c4 * 4];
#pragma unroll
            for (int q = 0; q < 4; q++) {
                uint32_t h = f2tf32(av[q]);
                da[q] = h;
                dl[q] = f2tf32(av[q] - __uint_as_float(h));
            }
        }
#pragma unroll
        for (int i = 0; i < 2; i++) {
            int idx = i * 256 + tid;
            int row = idx >> 2, c4 = idx & 3;
            float4 v = *((const float4*)(g_proj_enc + ((size_t)b * SS + row) * HH + kt) + c4);
            float bv[4] = {v.x, v.y, v.z, v.w};
            uint32_t* db = &Bh[row * 20 + c4 * 4];
            uint32_t* dl = &Bl[row * 20 + c4 * 4];
#pragma unroll
            for (int q = 0; q < 4; q++) {
                uint32_t h = f2tf32(bv[q]);
                db[q] = h;
                dl[q] = f2tf32(bv[q] - __uint_as_float(h));
            }
        }
        __syncthreads();
#pragma unroll
        for (int ks = 0; ks < 2; ks++) {
            const int k0 = ks * 8;
            uint32_t ah[2][4], al2[2][4], bh[4][2], bl2[4][2];
#pragma unroll
            for (int mt = 0; mt < 2; mt++) {
                int rb = wm + mt * 16;
                ah[mt][0] = Ah[(rb + g) * 20 + k0 + tg];
                ah[mt][1] = Ah[(rb + g + 8) * 20 + k0 + tg];
                ah[mt][2] = Ah[(rb + g) * 20 + k0 + tg + 4];
                ah[mt][3] = Ah[(rb + g + 8) * 20 + k0 + tg + 4];
                al2[mt][0] = Al[(rb + g) * 20 + k0 + tg];
                al2[mt][1] = Al[(rb + g + 8) * 20 + k0 + tg];
                al2[mt][2] = Al[(rb + g) * 20 + k0 + tg + 4];
                al2[mt][3] = Al[(rb + g + 8) * 20 + k0 + tg + 4];
            }
#pragma unroll
            for (int nt = 0; nt < 4; nt++) {
                int nb = wn + nt * 8 + g;
                bh[nt][0] = Bh[nb * 20 + k0 + tg];
                bh[nt][1] = Bh[nb * 20 + k0 + tg + 4];
                bl2[nt][0] = Bl[nb * 20 + k0 + tg];
                bl2[nt][1] = Bl[nb * 20 + k0 + tg + 4];
            }
#pragma unroll
            for (int mt = 0; mt < 2; mt++)
#pragma unroll
                for (int nt = 0; nt < 4; nt++) {
                    mma_tf32(acc[mt][nt], ah[mt], bh[nt]);
                    mma_tf32(acc[mt][nt], al2[mt], bh[nt]);
                    mma_tf32(acc[mt][nt], ah[mt], bl2[nt]);
                }
        }
        __syncthreads();
    }

#pragma unroll
    for (int mt = 0; mt < 2; mt++)
#pragma unroll
        for (int nt = 0; nt < 4; nt++) {
            int row = wm + mt * 16 + g, col = wn + nt * 8 + 2 * tg;
            sc[row * 132 + col] = acc[mt][nt][0];
            sc[row * 132 + col + 1] = acc[mt][nt][1];
            sc[(row + 8) * 132 + col] = acc[mt][nt][2];
            sc[(row + 8) * 132 + col + 1] = acc[mt][nt][3];
        }
    __syncthreads();

    const int len = lens[b];
    for (int i = 0; i < 8; i++) {
        int t = warp * 8 + i;
        float v[4], mx = -3.0e38f;
#pragma unroll
        for (int q = 0; q < 4; q++) {
            int s = lane + q * 32;
            v[q] = (s < len) ? sc[t * 132 + s] : -3.0e38f;
            mx = fmaxf(mx, v[q]);
        }
        for (int off = 16; off > 0; off >>= 1)
            mx = fmaxf(mx, __shfl_xor_sync(0xFFFFFFFFu, mx, off));
        float e[4], sum = 0.0f;
#pragma unroll
        for (int q = 0; q < 4; q++) {
            int s = lane + q * 32;
            e[q] = (s < len) ? expf(v[q] - mx) : 0.0f;
            sum += e[q];
        }
        for (int off = 16; off > 0; off >>= 1)
            sum += __shfl_xor_sync(0xFFFFFFFFu, sum, off);
        float inv = 1.0f / sum;
#pragma unroll
        for (int q = 0; q < 4; q++)
            g_att2[((size_t)b * TT + t) * SS + lane + q * 32] = e[q] * inv;
    }
}

// ---------------- post-loop: HO = tf32_round(HO + att @ proj2) ----------
__global__ __launch_bounds__(256) void k_ctx()
{
    __shared__ float att_sh[TT * SS];
    const int b = blockIdx.y, jt = blockIdx.x, tid = threadIdx.x;

    for (int i = tid; i < TT * SS / 4; i += 256)
        ((float4*)att_sh)[i] = ((const float4*)(g_att2 + (size_t)b * TT * SS))[i];
    __syncthreads();

    const int j = jt * 128 + (tid & 127);
    const int th = tid >> 7;
    float acc[32];
#pragma unroll
    for (int tt = 0; tt < 32; tt++) acc[tt] = 0.0f;

    const float* p2 = g_proj2 + (size_t)b * SS * HH + j;
    const float* ar = att_sh + (th * 32) * SS;
#pragma unroll 4
    for (int s = 0; s < SS; s++) {
        float v = p2[(size_t)s * HH];
#pragma unroll
        for (int tt = 0; tt < 32; tt++)
            acc[tt] += ar[tt * SS + s] * v;
    }
#pragma unroll
    for (int tt = 0; tt < 32; tt++) {
        size_t o = ((size_t)b * TT + th * 32 + tt) * HH + j;
        g_ho[o] = __uint_as_float(f2tf32(g_ho[o] + acc[tt]));
    }
}

// ---------------- launcher ----------------
extern "C" void kernel_launch(void* const* d_in, const int* in_sizes, int n_in,
                              void* d_out, int out_size)
{
    const int* tok = (const int*)d_in[0];
    const float* enc = (const float*)d_in[1];
    const int* lens = (const int*)d_in[2];
    const float* h0 = (const float*)d_in[3];
    const float* c0 = (const float*)d_in[4];
    const float* emb = (const float*)d_in[5];
    const float* Wih = (const float*)d_in[6];
    const float* Whh = (const float*)d_in[7];
    const float* bih = (const float*)d_in[8];
    const float* bhh = (const float*)d_in[9];
    const float* Wa = (const float*)d_in[10];
    const float* Wcw = (const float*)d_in[11];
    const float* Wcb = (const float*)d_in[12];
    const float* Wow = (const float*)d_in[13];
    const float* Wob = (const float*)d_in[14];
    float* out = (float*)d_out;

    float *p_gatesx, *p_hhist, *p_ho, *p_bias, *p_wor;
    cudaGetSymbolAddress((void**)&p_gatesx, g_gatesx);
    cudaGetSymbolAddress((void**)&p_hhist, g_hhist);
    cudaGetSymbolAddress((void**)&p_ho, g_ho);
    cudaGetSymbolAddress((void**)&p_bias, g_bias2);
    cudaGetSymbolAddress((void**)&p_wor, g_wo_r);

    // smem opt-ins (one per instantiation!)
    const int NC_DYN = 2 * 2 * (128 * 36) * 4;          // 73,728 B
    const int CP_DYN = 2 * 2 * (2 * 128 * 20) * 4;      // 81,920 B
    cudaFuncSetAttribute(gemm_nc<true,  false>, cudaFuncAttributeMaxDynamicSharedMemorySize, NC_DYN);
    cudaFuncSetAttribute(gemm_nc<false, true>,  cudaFuncAttributeMaxDynamicSharedMemorySize, NC_DYN);
    cudaFuncSetAttribute(gemm_comp,             cudaFuncAttributeMaxDynamicSharedMemorySize, CP_DYN);
    cudaFuncSetAttribute(k_mega,                cudaFuncAttributeMaxDynamicSharedMemorySize, CP_DYN);
    const int SC_DYN = 64 * 132 * 4;                    // 33,792 B
    cudaFuncSetAttribute(k_scores, cudaFuncAttributeMaxDynamicSharedMemorySize, SC_DYN);

    // #1: fused prep (packed B' + bias + barrier reset)
    k_prep_all<<<(2048 * 128 + 255) / 256, 256>>>(Whh, bih, bhh);
    // #2: h0 fragment planes
    k_prep_h0<<<(BB * HH + 255) / 256, 256>>>(h0);
    // #3: A1 gates_x = emb[tok] @ W_ih^T + (b_ih + b_hh)
    gemm_nc<true, false><<<dim3(4 * HH / 128, BB * TT / 128), 256, NC_DYN>>>(
        emb, EE, tok, Wih, EE, p_gatesx, 4 * HH, p_bias, EE);
    // #4: MEGA — decode (32 blocks) overlapped with A2/A3/prep_wo (384 blocks)
    k_mega<<<NDEC + 384, 256, CP_DYN>>>(c0, enc, Wa, Wcw, Wow);

    // #5: scores + softmax
    k_scores<<<BB, 256, SC_DYN>>>(lens);
    // #6: HO = Hhist @ Wc_h^T + Wcb (compensated)
    gemm_comp<<<dim3(HH / 128, BB * TT / 128), 256, CP_DYN>>>(
        p_hhist, HH, Wcw, HH + ENCC, p_ho, HH, Wcb, HH);
    // #7: HO = tf32_round(HO + att @ proj2)
    k_ctx<<<dim3(4, BB), 256>>>();
    // #8: D logits = HO @ Wo^T + Wo_b (pre-rounded: bit-copy staging)
    gemm_nc<false, true><<<dim3(VV / 128, BB * TT / 128), 256, NC_DYN>>>(
        p_ho, HH, nullptr, p_wor, HH, out, VV, Wob, HH);
}